// round 10
// baseline (speedup 1.0000x reference)
#include <cuda_runtime.h>
#include <cuda_fp16.h>

// Residual VQ (L=8, G=2, K=1024, D=256), B=16, T=4096, N=65536.
// Single fp16 mma.sync GEMM (e pre-scaled by 1024; validated round 9)
// inside the round-7 proven skeleton (cp.async double-buffer + ldmatrix +
// shuffle top-2-per-column epilogue). Per-token running top-8; sound margin;
// group-aware exact fp32 reference-semantics rescue (sequential d-ascending
// FMA chain, d = fl(fl(a+b)-2c), first-index argmin).

#define LL 8
#define GG 2
#define KK 1024
#define DD 256
#define TT 4096
#define NTOK 65536ull
#define TILE 64
#define NTH 256
#define APITCH 264      // fp16 per A row (256 + 8 pad) -> 528B
#define BPITCH 72       // fp16 per B row (64 + 8 pad)  -> 144B
#define BSTAGE 18432    // 128 * BPITCH * 2B

#define QOUT_ELEMS 33554432ull
#define LOSS_OFF   33554432ull
#define IDX_OFF    33554433ull

#define CBELEMS (LL * GG * KK * DD)

// smem byte offsets
#define OFF_X    0          // fp32 [256][64]   65536
#define OFF_AH   65536      // fp16 [64][264]   33792
#define OFF_B    99328      // 2 x BSTAGE       36864
#define OFF_E2S  136192     // fp32 [128]
#define OFF_ASM  136704     // fp32 [64]
#define OFF_PV   136960     // fp32 [64][8]
#define OFF_PI   139008     // int  [64][8]
#define OFF_RUNI 141056     // int  [64]
#define OFF_RED  141312     // double [256]
#define SMEM_TOT 143360

__device__ float   g_e2[LL * GG * KK];
__device__ double  g_loss[2048];
__device__ __half  g_eh[CBELEMS];     // fl16(1024 * e)

// ---------------------------------------------------------------- asm helpers
__device__ __forceinline__ void mma16816h(float* c, const unsigned* a, const unsigned* b) {
    asm volatile(
        "mma.sync.aligned.m16n8k16.row.col.f32.f16.f16.f32 "
        "{%0,%1,%2,%3},{%4,%5,%6,%7},{%8,%9},{%0,%1,%2,%3};"
        : "+f"(c[0]), "+f"(c[1]), "+f"(c[2]), "+f"(c[3])
        : "r"(a[0]), "r"(a[1]), "r"(a[2]), "r"(a[3]), "r"(b[0]), "r"(b[1]));
}
__device__ __forceinline__ void ldsm_x4(unsigned* r, unsigned addr) {
    asm volatile("ldmatrix.sync.aligned.m8n8.x4.shared.b16 {%0,%1,%2,%3},[%4];"
                 : "=r"(r[0]), "=r"(r[1]), "=r"(r[2]), "=r"(r[3]) : "r"(addr));
}
__device__ __forceinline__ void ldsm_x2(unsigned* r, unsigned addr) {
    asm volatile("ldmatrix.sync.aligned.m8n8.x2.shared.b16 {%0,%1},[%2];"
                 : "=r"(r[0]), "=r"(r[1]) : "r"(addr));
}
__device__ __forceinline__ void cpasync16(unsigned dst, const void* src) {
    asm volatile("cp.async.cg.shared.global [%0], [%1], 16;"
                 :: "r"(dst), "l"(__cvta_generic_to_global(src)));
}
__device__ __forceinline__ void merge2(float& v1, int& i1, float& v2, int& i2,
                                       float w1, int j1, float w2, int j2) {
    if (w1 < v1) {
        float t2 = v1; int ti2 = i1;
        v1 = w1; i1 = j1;
        if (w2 < t2) { v2 = w2; i2 = j2; } else { v2 = t2; i2 = ti2; }
    } else if (w1 < v2) {
        v2 = w1; i2 = j1;
    }
}

// ---------------------------------------------------------------- ||e||^2 (exact ref rounding)
__global__ void e2_kernel(const float* __restrict__ cb) {
    int c = blockIdx.x * blockDim.x + threadIdx.x;
    if (c >= LL * GG * KK) return;
    const float* e = cb + (size_t)c * DD;
    float s = 0.0f;
    for (int d = 0; d < DD; ++d) {
        float v = e[d];
        s = __fadd_rn(s, __fmul_rn(v, v));
    }
    g_e2[c] = s;
}

// ---------------------------------------------------------------- codebook fp16 (scaled 1024x)
__global__ void eh_kernel(const float* __restrict__ cb) {
    int i = blockIdx.x * blockDim.x + threadIdx.x;
    if (i >= CBELEMS) return;
    g_eh[i] = __float2half_rn(__fmul_rn(cb[i], 1024.0f));
}

// ---------------------------------------------------------------- main
__global__ void __launch_bounds__(NTH, 1)
rvq_kernel(const float* __restrict__ xin, const float* __restrict__ cb,
           float* __restrict__ dout, unsigned long long out_size) {
    extern __shared__ char smraw[];
    float*   X    = (float*)(smraw + OFF_X);
    __half*  Ah   = (__half*)(smraw + OFF_AH);
    float*   E2s  = (float*)(smraw + OFF_E2S);
    float*   Asm  = (float*)(smraw + OFF_ASM);
    float*   PV   = (float*)(smraw + OFF_PV);
    int*     PI   = (int*)(smraw + OFF_PI);
    int*     RUNI = (int*)(smraw + OFF_RUNI);
    double*  red  = (double*)(smraw + OFF_RED);

    const unsigned smbase = (unsigned)__cvta_generic_to_shared(smraw);
    const unsigned uB[2] = {smbase + OFF_B, smbase + OFF_B + BSTAGE};

    const int tid  = threadIdx.x;
    const int lane = tid & 31;
    const int warp = tid >> 5;
    const int wm   = warp >> 2;           // 0..1  (32 token rows)
    const int wn   = warp & 3;            // 0..3  (32 code cols)
    const int r4   = lane >> 2;           // 0..7
    const int kq   = lane & 3;            // 0..3

    // ldmatrix lane address components (verified in rounds 7/9)
    const int lrowA  = (lane & 7) + (((lane >> 3) & 1) << 3);
    const int lkoffA = (lane >> 4) << 3;
    const unsigned aBase = smbase + OFF_AH +
        (unsigned)(((wm * 32 + lrowA) * APITCH + lkoffA) << 1);
    const int rB   = lane & 7;
    const int selB = (lane >> 3) & 1;
    const unsigned bLaneOff = (unsigned)(((wn * 32 + rB) * BPITCH + selB * 8) << 1);

    const int g    = blockIdx.y;
    const int tile = blockIdx.x;
    const int b    = tile >> 6;
    const int t0   = (tile & 63) << 6;
    const float* xb = xin + ((size_t)b * (GG * DD) + (size_t)g * DD) * TT + t0;

    for (int i = tid; i < DD * TILE; i += NTH) {
        int d = i >> 6, t = i & 63;
        X[i] = xb[(size_t)d * TT + t];
    }
    __syncthreads();

    double lacc = 0.0;

    for (int l = 0; l < LL; ++l) {
        const int    cbase = (l * GG + g) * KK;
        const float* cbl   = cb + (size_t)cbase * DD;

        // exact a_n = sequential fl(x^2) sum, d ascending (ref reduce order)
        if (tid < TILE) {
            float s = 0.0f;
            const float* xc = X + tid;
#pragma unroll 8
            for (int d = 0; d < DD; ++d) {
                float v = xc[d * TILE];
                s = __fadd_rn(s, __fmul_rn(v, v));
            }
            Asm[tid] = s;
        }
        // residual -> fp16 A
        for (int i = tid; i < DD * TILE; i += NTH) {
            int d = i >> 6, t = i & 63;
            Ah[t * APITCH + d] = __float2half_rn(X[d * TILE + t]);
        }
        __syncthreads();

        // per-token running top-8 (explicit scalars, tid<64)
        float v0 = 3.0e38f, v1 = 3.0e38f, v2 = 3.0e38f, v3 = 3.0e38f,
              v4 = 3.0e38f, v5 = 3.0e38f, v6 = 3.0e38f, v7 = 3.0e38f;
        int   i0 = 0, i1 = 0, i2 = 0, i3 = 0, i4 = 0, i5 = 0, i6 = 0, i7 = 0;

        for (int kb = 0; kb < 8; ++kb) {               // 8 blocks of 128 codes
            const size_t gbBlk = ((size_t)(cbase + kb * 128)) * DD;
            if (tid < 128) E2s[tid] = g_e2[cbase + kb * 128 + tid];

            // issue chunk 0 into stage 0
            {
                const __half* sH = g_eh + gbBlk;
#pragma unroll
                for (int it = 0; it < 4; ++it) {
                    int v = tid + it * NTH;
                    int code = v >> 3, d8 = (v & 7) * 8;
                    cpasync16(uB[0] + (unsigned)((code * BPITCH + d8) << 1),
                              sH + (size_t)code * DD + d8);
                }
                asm volatile("cp.async.commit_group;");
            }

            float acc[2][4][4];
#pragma unroll
            for (int mt = 0; mt < 2; ++mt)
#pragma unroll
                for (int nt = 0; nt < 4; ++nt)
#pragma unroll
                    for (int e = 0; e < 4; ++e) acc[mt][nt][e] = 0.f;

#pragma unroll 1
            for (int kc = 0; kc < 4; ++kc) {           // 4 d-chunks of 64
                if (kc < 3) {                          // prefetch next chunk
                    const __half* sH = g_eh + gbBlk + (kc + 1) * 64;
                    unsigned dh = uB[(kc + 1) & 1];
#pragma unroll
                    for (int it = 0; it < 4; ++it) {
                        int v = tid + it * NTH;
                        int code = v >> 3, d8 = (v & 7) * 8;
                        cpasync16(dh + (unsigned)((code * BPITCH + d8) << 1),
                                  sH + (size_t)code * DD + d8);
                    }
                    asm volatile("cp.async.commit_group;");
                    asm volatile("cp.async.wait_group 1;");
                } else {
                    asm volatile("cp.async.wait_group 0;");
                }
                __syncthreads();

                const unsigned b_st = uB[kc & 1] + bLaneOff;
#pragma unroll
                for (int ks = 0; ks < 4; ++ks) {       // k16 steps
                    const unsigned akoff = (unsigned)((kc * 64 + ks * 16) << 1);
                    const unsigned bkoff = (unsigned)((ks * 16) << 1);
                    unsigned ah[2][4], bh[4][2];
#pragma unroll
                    for (int mt = 0; mt < 2; ++mt)
                        ldsm_x4(ah[mt], aBase + (unsigned)(mt * 16 * APITCH * 2) + akoff);
#pragma unroll
                    for (int nt = 0; nt < 4; ++nt)
                        ldsm_x2(bh[nt], b_st + (unsigned)(nt * 8 * BPITCH * 2) + bkoff);
#pragma unroll
                    for (int mt = 0; mt < 2; ++mt)
#pragma unroll
                        for (int nt = 0; nt < 4; ++nt)
                            mma16816h(acc[mt][nt], ah[mt], bh[nt]);
                }
                __syncthreads();
            }

            // epilogue (round-7 proven): distances + per-warp-column top2
#pragma unroll
            for (int mt = 0; mt < 2; ++mt)
#pragma unroll
                for (int h = 0; h < 2; ++h) {
                    int row = wm * 32 + mt * 16 + h * 8 + r4;
                    float a_tok = Asm[row];
                    float w1 = 3.0e38f, w2 = 3.0e38f; int j1 = 0, j2 = 0;
#pragma unroll
                    for (int nt = 0; nt < 4; ++nt)
#pragma unroll
                        for (int j = 0; j < 2; ++j) {
                            int colq = wn * 32 + nt * 8 + 2 * kq + j;
                            float c = acc[mt][nt][h * 2 + j];
                            // d~ = fl( fl(a+b) - 2*(c~/1024) ), /1024 exact
                            float dv = __fadd_rn(__fadd_rn(a_tok, E2s[colq]),
                                                 __fmul_rn(c, -0.001953125f));
                            int idx = kb * 128 + colq;
                            if (dv < w1) { w2 = w1; j2 = j1; w1 = dv; j1 = idx; }
                            else if (dv < w2) { w2 = dv; j2 = idx; }
                        }
#pragma unroll
                    for (int s = 1; s <= 2; s <<= 1) {
                        float u1 = __shfl_xor_sync(0xffffffffu, w1, s);
                        int   k1 = __shfl_xor_sync(0xffffffffu, j1, s);
                        float u2 = __shfl_xor_sync(0xffffffffu, w2, s);
                        int   k2 = __shfl_xor_sync(0xffffffffu, j2, s);
                        merge2(w1, j1, w2, j2, u1, k1, u2, k2);
                    }
                    if (kq == 0) {
                        PV[row * 8 + wn * 2 + 0] = w1;  PI[row * 8 + wn * 2 + 0] = j1;
                        PV[row * 8 + wn * 2 + 1] = w2;  PI[row * 8 + wn * 2 + 1] = j2;
                    }
                }
            __syncthreads();
            if (tid < TILE) {                          // merge 8 partials into top8
#pragma unroll
                for (int e = 0; e < 8; ++e) {
                    float dv = PV[tid * 8 + e]; int idx = PI[tid * 8 + e];
                    if (dv < v7) {
                        v7 = dv; i7 = idx;
                        if (v7 < v6) { float t = v6; v6 = v7; v7 = t; int ti = i6; i6 = i7; i7 = ti; }
                        if (v6 < v5) { float t = v5; v5 = v6; v6 = t; int ti = i5; i5 = i6; i6 = ti; }
                        if (v5 < v4) { float t = v4; v4 = v5; v5 = t; int ti = i4; i4 = i5; i5 = ti; }
                        if (v4 < v3) { float t = v3; v3 = v4; v4 = t; int ti = i3; i3 = i4; i4 = ti; }
                        if (v3 < v2) { float t = v2; v2 = v3; v3 = t; int ti = i2; i2 = i3; i3 = ti; }
                        if (v2 < v1) { float t = v1; v1 = v2; v2 = t; int ti = i1; i1 = i2; i2 = ti; }
                        if (v1 < v0) { float t = v0; v0 = v1; v1 = t; int ti = i0; i0 = i1; i1 = ti; }
                    }
                }
            }
            __syncthreads();
        }

        // finalize winner: sound margin; group-aware exact rescue
        if (tid < TILE) {
            float a_tok  = Asm[tid];
            float margin = __fmaf_rn(sqrtf(a_tok), 4.0e-5f,
                           __fmaf_rn(a_tok, 5.0e-7f, 2.0e-5f));
            float thr = v0 + margin;
            int winner = i0;
            if (v1 <= thr) {
                bool fullscan = (v7 <= thr);
                int codes[104]; int m = 0;
                if (!fullscan) {
                    float vv[8] = {v0, v1, v2, v3, v4, v5, v6, v7};
                    int   ii[8] = {i0, i1, i2, i3, i4, i5, i6, i7};
                    int cand[8]; int nc = 0;
#pragma unroll
                    for (int i = 0; i < 8; ++i)
                        if (vv[i] <= thr) cand[nc++] = ii[i];
                    // columns (32-code groups) holding >=2 candidates may hide
                    // a truncated 3rd in-margin code -> scan whole group
                    int glist[4]; int ng = 0;
                    for (int i = 0; i < nc && !fullscan; ++i)
                        for (int j = i + 1; j < nc; ++j)
                            if ((cand[i] >> 5) == (cand[j] >> 5)) {
                                int gg2 = cand[i] >> 5;
                                bool have = false;
                                for (int q = 0; q < ng; ++q)
                                    if (glist[q] == gg2) have = true;
                                if (!have) {
                                    if (ng >= 3) { fullscan = true; break; }
                                    glist[ng++] = gg2;
                                }
                            }
                    if (!fullscan) {
                        for (int i = 0; i < nc; ++i) {
                            bool ingrp = false;
                            for (int q = 0; q < ng; ++q)
                                if ((cand[i] >> 5) == glist[q]) ingrp = true;
                            if (!ingrp) codes[m++] = cand[i];
                        }
                        for (int q = 0; q < ng; ++q)
                            for (int k = 0; k < 32; ++k)
                                codes[m++] = glist[q] * 32 + k;
                        for (int i = 1; i < m; ++i) {   // sort ascending index
                            int key = codes[i], j = i - 1;
                            while (j >= 0 && codes[j] > key) {
                                codes[j + 1] = codes[j]; --j;
                            }
                            codes[j + 1] = key;
                        }
                    }
                }
                if (fullscan) {
                    float best = 3.0e38f; winner = 0;
                    for (int code = 0; code < KK; ++code) {
                        const float* ev = cbl + (size_t)code * DD;
                        const float* xc = X + tid;
                        float c = 0.0f;
                        for (int d = 0; d < DD; ++d)
                            c = __fmaf_rn(xc[d * TILE], ev[d], c);
                        float dv = __fadd_rn(__fadd_rn(a_tok, g_e2[cbase + code]),
                                             __fmul_rn(-2.0f, c));
                        if (dv < best) { best = dv; winner = code; }
                    }
                } else {
                    float best = 3.0e38f; winner = codes[0];
                    for (int cc = 0; cc < m; ++cc) {
                        int code = codes[cc];
                        const float* ev = cbl + (size_t)code * DD;
                        const float* xc = X + tid;
                        float c = 0.0f;
#pragma unroll 8
                        for (int d = 0; d < DD; ++d)
                            c = __fmaf_rn(xc[d * TILE], ev[d], c);
                        float dv = __fadd_rn(__fadd_rn(a_tok, g_e2[cbase + code]),
                                             __fmul_rn(-2.0f, c));
                        if (dv < best) { best = dv; winner = code; }
                    }
                }
            }
            RUNI[tid] = winner;
            if (out_size > IDX_OFF) {
                size_t n = (size_t)b * TT + t0 + tid;
                size_t o = IDX_OFF + ((size_t)(l * GG + g)) * NTOK + n;
                if (o < out_size) dout[o] = (float)winner;
            }
        }
        __syncthreads();

        // residual update (reference STE elementwise)
        {
            int token = tid >> 2, dq = tid & 3;
            int code  = RUNI[token];
            const float* ev = cbl + (size_t)code * DD + dq * 64;
            float* xc = X + (dq * 64) * TILE + token;
#pragma unroll 8
            for (int dd = 0; dd < 64; ++dd) {
                float x  = xc[dd * TILE];
                float dl = __fsub_rn(ev[dd], x);
                float qn = __fadd_rn(x, dl);
                xc[dd * TILE] = __fsub_rn(x, qn);
                lacc += (double)dl * (double)dl;
            }
        }
        __syncthreads();
    }

    // quantized_out = xin - final residual
    for (int i = tid; i < DD * TILE; i += NTH) {
        int d = i >> 6, t = i & 63;
        size_t o = ((size_t)b * (GG * DD) + (size_t)g * DD + d) * TT + t0 + t;
        if (o < out_size && o < QOUT_ELEMS)
            dout[o] = __fsub_rn(xb[(size_t)d * TT + t], X[i]);
    }

    // deterministic per-CTA loss partial
    red[tid] = lacc;
    __syncthreads();
    for (int s = 128; s > 0; s >>= 1) {
        if (tid < s) red[tid] += red[tid + s];
        __syncthreads();
    }
    if (tid == 0) g_loss[blockIdx.y * 1024 + blockIdx.x] = red[0];
}

// ---------------------------------------------------------------- loss reduce
__global__ void loss_kernel(float* __restrict__ dout, unsigned long long out_size) {
    __shared__ double red[256];
    int tid = threadIdx.x;
    double s = 0.0;
    for (int i = tid; i < 2048; i += 256) s += g_loss[i];
    red[tid] = s;
    __syncthreads();
    for (int st = 128; st > 0; st >>= 1) {
        if (tid < st) red[tid] += red[tid + st];
        __syncthreads();
    }
    if (tid == 0 && out_size > LOSS_OFF)
        dout[LOSS_OFF] = (float)(1.25 * red[0] / (8.0 * 33554432.0));
}

// ---------------------------------------------------------------- launch
extern "C" void kernel_launch(void* const* d_in, const int* in_sizes, int n_in,
                              void* d_out, int out_size) {
    const float* xin = (const float*)d_in[0];
    const float* cb  = (const float*)d_in[1];
    if (n_in >= 2 && in_sizes[0] == CBELEMS) {
        xin = (const float*)d_in[1];
        cb  = (const float*)d_in[0];
    }
    float* dout = (float*)d_out;
    unsigned long long osz = (unsigned long long)out_size;

    static bool attr_set = false;
    if (!attr_set) {
        cudaFuncSetAttribute(rvq_kernel, cudaFuncAttributeMaxDynamicSharedMemorySize,
                             SMEM_TOT);
        attr_set = true;
    }

    e2_kernel<<<(LL * GG * KK + 255) / 256, 256>>>(cb);
    eh_kernel<<<(CBELEMS + 255) / 256, 256>>>(cb);
    dim3 grid(1024, GG);
    rvq_kernel<<<grid, NTH, SMEM_TOT>>>(xin, cb, dout, osz);
    loss_kernel<<<1, 256>>>(dout, osz);
}

// round 11
// speedup vs baseline: 1.6593x; 1.6593x over previous
#include <cuda_runtime.h>
#include <cuda_bf16.h>

// Residual VQ (L=8, G=2, K=1024, D=256), B=16, T=4096, N=65536.
// bf16 split MMA (xh*eh + xh*el + xl*eh, fp32 accum) -> approx distances;
// sound margin -> <=3 candidates -> exact fp32 reference-semantics rescore.
// Round 11: M=128 tokens/CTA (halves CTA count / fixed overhead); exact fp32
// residual lives in __device__ global scratch (L2-hot), SMEM holds A splits + B.

#define LL 8
#define GG 2
#define KK 1024
#define DD 256
#define TT 4096
#define NTOK 65536ull
#define TILE 128
#define NTH 256
#define APITCH 264      // bf16 per A row (256 + 8 pad) -> 528B
#define BPITCH 72       // bf16 per B row (64 + 8 pad)  -> 144B
#define BSTAGE 18432    // 128 codes * BPITCH * 2B (one split, one stage)

#define QOUT_ELEMS 33554432ull
#define LOSS_OFF   33554432ull
#define IDX_OFF    33554433ull

#define CBELEMS (LL * GG * KK * DD)
#define NCTA 1024

// smem byte offsets
#define OFF_AH   0          // bf16 [128][264]  67584
#define OFF_AL   67584      // bf16 [128][264]  67584
#define OFF_B    135168     // 2 stages x (H 18432 + L 18432) = 73728
#define OFF_E2S  208896     // fp32 [128]
#define OFF_ASM  209408     // fp32 [128]
#define OFF_PV   209920     // fp32 [128][8]
#define OFF_PI   214016     // int  [128][8]
#define OFF_RUNI 218112     // int  [128]
#define OFF_RED  218624     // double [256]
#define SMEM_TOT 220672

__device__ float          g_e2[LL * GG * KK];
__device__ double         g_loss[NCTA];
__device__ __nv_bfloat16  g_ehi[CBELEMS];
__device__ __nv_bfloat16  g_elo[CBELEMS];
__device__ float          g_X[(size_t)NCTA * DD * TILE];   // per-CTA residual [d][t]

// ---------------------------------------------------------------- asm helpers
__device__ __forceinline__ void mma16816(float* c, const unsigned* a, const unsigned* b) {
    asm volatile(
        "mma.sync.aligned.m16n8k16.row.col.f32.bf16.bf16.f32 "
        "{%0,%1,%2,%3},{%4,%5,%6,%7},{%8,%9},{%0,%1,%2,%3};"
        : "+f"(c[0]), "+f"(c[1]), "+f"(c[2]), "+f"(c[3])
        : "r"(a[0]), "r"(a[1]), "r"(a[2]), "r"(a[3]), "r"(b[0]), "r"(b[1]));
}
__device__ __forceinline__ void ldsm_x4(unsigned* r, unsigned addr) {
    asm volatile("ldmatrix.sync.aligned.m8n8.x4.shared.b16 {%0,%1,%2,%3},[%4];"
                 : "=r"(r[0]), "=r"(r[1]), "=r"(r[2]), "=r"(r[3]) : "r"(addr));
}
__device__ __forceinline__ void ldsm_x2(unsigned* r, unsigned addr) {
    asm volatile("ldmatrix.sync.aligned.m8n8.x2.shared.b16 {%0,%1},[%2];"
                 : "=r"(r[0]), "=r"(r[1]) : "r"(addr));
}
__device__ __forceinline__ void cpasync16(unsigned dst, const void* src) {
    asm volatile("cp.async.cg.shared.global [%0], [%1], 16;"
                 :: "r"(dst), "l"(__cvta_generic_to_global(src)));
}
__device__ __forceinline__ void merge2(float& v1, int& i1, float& v2, int& i2,
                                       float w1, int j1, float w2, int j2) {
    if (w1 < v1) {
        float t2 = v1; int ti2 = i1;
        v1 = w1; i1 = j1;
        if (w2 < t2) { v2 = w2; i2 = j2; } else { v2 = t2; i2 = ti2; }
    } else if (w1 < v2) {
        v2 = w1; i2 = j1;
    }
}

// ---------------------------------------------------------------- ||e||^2 (exact ref rounding)
__global__ void e2_kernel(const float* __restrict__ cb) {
    int c = blockIdx.x * blockDim.x + threadIdx.x;
    if (c >= LL * GG * KK) return;
    const float* e = cb + (size_t)c * DD;
    float s = 0.0f;
    for (int d = 0; d < DD; ++d) {
        float v = e[d];
        s = __fadd_rn(s, __fmul_rn(v, v));
    }
    g_e2[c] = s;
}

// ---------------------------------------------------------------- codebook bf16 split
__global__ void split_e_kernel(const float* __restrict__ cb) {
    int i = blockIdx.x * blockDim.x + threadIdx.x;
    if (i >= CBELEMS) return;
    float v = cb[i];
    __nv_bfloat16 h = __float2bfloat16_rn(v);
    float r = __fsub_rn(v, __bfloat162float(h));
    g_ehi[i] = h;
    g_elo[i] = __float2bfloat16_rn(r);
}

// ---------------------------------------------------------------- main
__global__ void __launch_bounds__(NTH, 1)
rvq_kernel(const float* __restrict__ xin, const float* __restrict__ cb,
           float* __restrict__ dout, unsigned long long out_size) {
    extern __shared__ char smraw[];
    __nv_bfloat16*  Ah   = (__nv_bfloat16*)(smraw + OFF_AH);
    __nv_bfloat16*  Al   = (__nv_bfloat16*)(smraw + OFF_AL);
    float*          E2s  = (float*)(smraw + OFF_E2S);
    float*          Asm  = (float*)(smraw + OFF_ASM);
    float*          PV   = (float*)(smraw + OFF_PV);
    int*            PI   = (int*)(smraw + OFF_PI);
    int*            RUNI = (int*)(smraw + OFF_RUNI);
    double*         red  = (double*)(smraw + OFF_RED);

    const unsigned smbase = (unsigned)__cvta_generic_to_shared(smraw);
    const unsigned uBH[2] = {smbase + OFF_B, smbase + OFF_B + 2 * BSTAGE};

    const int tid  = threadIdx.x;
    const int lane = tid & 31;
    const int warp = tid >> 5;
    const int wm   = warp >> 2;           // 0..1  (64 token rows each)
    const int wn   = warp & 3;            // 0..3  (32 code cols)
    const int r4   = lane >> 2;           // 0..7
    const int kq   = lane & 3;            // 0..3

    // ldmatrix lane address components (mapping verified rounds 7/9/10)
    const int lrowA  = (lane & 7) + (((lane >> 3) & 1) << 3);
    const int lkoffA = (lane >> 4) << 3;
    const unsigned aBaseH = smbase + OFF_AH +
        (unsigned)(((wm * 64 + lrowA) * APITCH + lkoffA) << 1);
    const unsigned aBaseL = smbase + OFF_AL +
        (unsigned)(((wm * 64 + lrowA) * APITCH + lkoffA) << 1);
    const int rB   = lane & 7;
    const int selB = (lane >> 3) & 1;
    const unsigned bLaneOff = (unsigned)(((wn * 32 + rB) * BPITCH + selB * 8) << 1);

    const int g    = blockIdx.y;
    const int tile = blockIdx.x;              // 0..511
    const int b    = tile >> 5;               // 32 tiles of 128 per batch row
    const int t0   = (tile & 31) << 7;
    const int cta  = g * 512 + tile;
    const float* xb = xin + ((size_t)b * (GG * DD) + (size_t)g * DD) * TT + t0;
    float* gX = g_X + (size_t)cta * (DD * TILE);

    // residual := xin tile, [d][t] in global scratch (both sides coalesced)
    for (int i = tid; i < DD * TILE; i += NTH) {
        int d = i >> 7, t = i & 127;
        gX[i] = xb[(size_t)d * TT + t];
    }
    __syncthreads();

    double lacc = 0.0;

    for (int l = 0; l < LL; ++l) {
        const int    cbase = (l * GG + g) * KK;
        const float* cbl   = cb + (size_t)cbase * DD;

        // exact a_n = sequential fl(x^2) sum, d ascending (ref reduce order)
        if (tid < TILE) {
            float s = 0.0f;
            const float* xc = gX + tid;
#pragma unroll 8
            for (int d = 0; d < DD; ++d) {
                float v = xc[d * TILE];
                s = __fadd_rn(s, __fmul_rn(v, v));
            }
            Asm[tid] = s;
        }
        // split residual into A_hi/A_lo bf16 [token][d]
        for (int i = tid; i < DD * TILE; i += NTH) {
            int d = i >> 7, t = i & 127;
            float v = gX[i];
            __nv_bfloat16 h = __float2bfloat16_rn(v);
            float rlo = __fsub_rn(v, __bfloat162float(h));
            Ah[t * APITCH + d] = h;
            Al[t * APITCH + d] = __float2bfloat16_rn(rlo);
        }
        __syncthreads();

        // per-token running top-3 (registers, tid<128)
        float t3v0 = 3.0e38f, t3v1 = 3.0e38f, t3v2 = 3.0e38f;
        int   t3i0 = 0,       t3i1 = 0,       t3i2 = 0;

        for (int kb = 0; kb < 8; ++kb) {               // 8 blocks of 128 codes
            const size_t gbBlk = ((size_t)(cbase + kb * 128)) * DD;
            if (tid < 128) E2s[tid] = g_e2[cbase + kb * 128 + tid];

            // issue chunk 0 into stage 0
            {
                const __nv_bfloat16* sH = g_ehi + gbBlk;
                const __nv_bfloat16* sL = g_elo + gbBlk;
#pragma unroll
                for (int it = 0; it < 4; ++it) {
                    int v = tid + it * NTH;
                    int code = v >> 3, d8 = (v & 7) * 8;
                    unsigned doff = (unsigned)((code * BPITCH + d8) << 1);
                    cpasync16(uBH[0] + doff, sH + (size_t)code * DD + d8);
                    cpasync16(uBH[0] + BSTAGE + doff, sL + (size_t)code * DD + d8);
                }
                asm volatile("cp.async.commit_group;");
            }

            float acc[4][4][4];
#pragma unroll
            for (int mt = 0; mt < 4; ++mt)
#pragma unroll
                for (int nt = 0; nt < 4; ++nt)
#pragma unroll
                    for (int e = 0; e < 4; ++e) acc[mt][nt][e] = 0.f;

#pragma unroll 1
            for (int kc = 0; kc < 4; ++kc) {           // 4 d-chunks of 64
                if (kc < 3) {                          // prefetch next chunk
                    const __nv_bfloat16* sH = g_ehi + gbBlk + (kc + 1) * 64;
                    const __nv_bfloat16* sL = g_elo + gbBlk + (kc + 1) * 64;
                    unsigned dh = uBH[(kc + 1) & 1];
#pragma unroll
                    for (int it = 0; it < 4; ++it) {
                        int v = tid + it * NTH;
                        int code = v >> 3, d8 = (v & 7) * 8;
                        unsigned doff = (unsigned)((code * BPITCH + d8) << 1);
                        cpasync16(dh + doff, sH + (size_t)code * DD + d8);
                        cpasync16(dh + BSTAGE + doff, sL + (size_t)code * DD + d8);
                    }
                    asm volatile("cp.async.commit_group;");
                    asm volatile("cp.async.wait_group 1;");
                } else {
                    asm volatile("cp.async.wait_group 0;");
                }
                __syncthreads();

                const unsigned bh_st = uBH[kc & 1] + bLaneOff;
                const unsigned bl_st = bh_st + BSTAGE;
#pragma unroll
                for (int ks = 0; ks < 4; ++ks) {       // k16 steps
                    const unsigned akoff = (unsigned)((kc * 64 + ks * 16) << 1);
                    const unsigned bkoff = (unsigned)((ks * 16) << 1);
                    unsigned ah[4][4], al[4][4], bh[4][2], bl[4][2];
#pragma unroll
                    for (int mt = 0; mt < 4; ++mt) {
                        ldsm_x4(ah[mt], aBaseH + (unsigned)(mt * 16 * APITCH * 2) + akoff);
                        ldsm_x4(al[mt], aBaseL + (unsigned)(mt * 16 * APITCH * 2) + akoff);
                    }
#pragma unroll
                    for (int nt = 0; nt < 4; ++nt) {
                        ldsm_x2(bh[nt], bh_st + (unsigned)(nt * 8 * BPITCH * 2) + bkoff);
                        ldsm_x2(bl[nt], bl_st + (unsigned)(nt * 8 * BPITCH * 2) + bkoff);
                    }
#pragma unroll
                    for (int mt = 0; mt < 4; ++mt)
#pragma unroll
                        for (int nt = 0; nt < 4; ++nt) {
                            mma16816(acc[mt][nt], ah[mt], bh[nt]);
                            mma16816(acc[mt][nt], ah[mt], bl[nt]);
                            mma16816(acc[mt][nt], al[mt], bh[nt]);
                        }
                }
                __syncthreads();
            }

            // epilogue: distances + per-warp per-row top2
#pragma unroll
            for (int mt = 0; mt < 4; ++mt)
#pragma unroll
                for (int h = 0; h < 2; ++h) {
                    int row = wm * 64 + mt * 16 + h * 8 + r4;
                    float a_tok = Asm[row];
                    float w1 = 3.0e38f, w2 = 3.0e38f; int j1 = 0, j2 = 0;
#pragma unroll
                    for (int nt = 0; nt < 4; ++nt)
#pragma unroll
                        for (int j = 0; j < 2; ++j) {
                            int colq = wn * 32 + nt * 8 + 2 * kq + j;
                            float c = acc[mt][nt][h * 2 + j];
                            float dv = __fadd_rn(__fadd_rn(a_tok, E2s[colq]),
                                                 __fmul_rn(-2.0f, c));
                            int idx = kb * 128 + colq;
                            if (dv < w1) { w2 = w1; j2 = j1; w1 = dv; j1 = idx; }
                            else if (dv < w2) { w2 = dv; j2 = idx; }
                        }
#pragma unroll
                    for (int s = 1; s <= 2; s <<= 1) {
                        float u1 = __shfl_xor_sync(0xffffffffu, w1, s);
                        int   k1 = __shfl_xor_sync(0xffffffffu, j1, s);
                        float u2 = __shfl_xor_sync(0xffffffffu, w2, s);
                        int   k2 = __shfl_xor_sync(0xffffffffu, j2, s);
                        merge2(w1, j1, w2, j2, u1, k1, u2, k2);
                    }
                    if (kq == 0) {
                        PV[row * 8 + wn * 2 + 0] = w1;  PI[row * 8 + wn * 2 + 0] = j1;
                        PV[row * 8 + wn * 2 + 1] = w2;  PI[row * 8 + wn * 2 + 1] = j2;
                    }
                }
            __syncthreads();
            if (tid < TILE) {                          // merge 8 partials into top3
#pragma unroll
                for (int e = 0; e < 8; ++e) {
                    float v = PV[tid * 8 + e]; int i = PI[tid * 8 + e];
                    if (v < t3v0) { t3v2 = t3v1; t3i2 = t3i1; t3v1 = t3v0; t3i1 = t3i0;
                                    t3v0 = v; t3i0 = i; }
                    else if (v < t3v1) { t3v2 = t3v1; t3i2 = t3i1; t3v1 = v; t3i1 = i; }
                    else if (v < t3v2) { t3v2 = v; t3i2 = i; }
                }
            }
            __syncthreads();
        }

        // finalize winner: sound margin; exact re-score for ambiguous tokens
        if (tid < TILE) {
            float a_tok  = Asm[tid];
            float margin = __fmaf_rn(a_tok, 2.4e-7f, 1.0e-5f);
            int winner = t3i0;
            if (t3v1 <= t3v0 + margin) {
                int ci[3]; int nc = 0;
                ci[nc++] = t3i0;
                ci[nc++] = t3i1;
                if (t3v2 <= t3v0 + margin) ci[nc++] = t3i2;
                if (nc == 3) {
                    int a0 = ci[0], a1 = ci[1], a2 = ci[2], t;
                    if (a1 < a0) { t = a0; a0 = a1; a1 = t; }
                    if (a2 < a1) { t = a1; a1 = a2; a2 = t; }
                    if (a1 < a0) { t = a0; a0 = a1; a1 = t; }
                    ci[0] = a0; ci[1] = a1; ci[2] = a2;
                } else if (ci[1] < ci[0]) { int t = ci[0]; ci[0] = ci[1]; ci[1] = t; }
                float best = 3.0e38f; winner = ci[0];
                for (int cc = 0; cc < nc; ++cc) {
                    int code = ci[cc];
                    const float* ev = cbl + (size_t)code * DD;
                    const float* xc = gX + tid;
                    float c = 0.0f;
#pragma unroll 8
                    for (int d = 0; d < DD; ++d)
                        c = __fmaf_rn(xc[d * TILE], ev[d], c);
                    float dv = __fadd_rn(__fadd_rn(a_tok, g_e2[cbase + code]),
                                         __fmul_rn(-2.0f, c));
                    if (dv < best) { best = dv; winner = code; }
                }
            }
            RUNI[tid] = winner;
            if (out_size > IDX_OFF) {
                size_t n = (size_t)b * TT + t0 + tid;
                size_t o = IDX_OFF + ((size_t)(l * GG + g)) * NTOK + n;
                if (o < out_size) dout[o] = (float)winner;
            }
        }
        __syncthreads();

        // residual update (reference STE elementwise):
        //   delta = fl(zq - x); quant = fl(x + delta); x' = fl(x - quant)
        {
            int token = tid >> 1, half = tid & 1;
            int code  = RUNI[token];
            const float* ev = cbl + (size_t)code * DD + half * 128;
            float* xc = gX + (half * 128) * TILE + token;
#pragma unroll 8
            for (int dd = 0; dd < 128; ++dd) {
                float x  = xc[dd * TILE];
                float dl = __fsub_rn(ev[dd], x);
                float qn = __fadd_rn(x, dl);
                xc[dd * TILE] = __fsub_rn(x, qn);
                lacc += (double)dl * (double)dl;
            }
        }
        __syncthreads();
    }

    // quantized_out = xin - final residual
    for (int i = tid; i < DD * TILE; i += NTH) {
        int d = i >> 7, t = i & 127;
        size_t o = ((size_t)b * (GG * DD) + (size_t)g * DD + d) * TT + t0 + t;
        if (o < out_size && o < QOUT_ELEMS)
            dout[o] = __fsub_rn(xb[(size_t)d * TT + t], gX[i]);
    }

    // deterministic per-CTA loss partial
    red[tid] = lacc;
    __syncthreads();
    for (int s = 128; s > 0; s >>= 1) {
        if (tid < s) red[tid] += red[tid + s];
        __syncthreads();
    }
    if (tid == 0) g_loss[cta] = red[0];
}

// ---------------------------------------------------------------- loss reduce
__global__ void loss_kernel(float* __restrict__ dout, unsigned long long out_size) {
    __shared__ double red[256];
    int tid = threadIdx.x;
    double s = 0.0;
    for (int i = tid; i < NCTA; i += 256) s += g_loss[i];
    red[tid] = s;
    __syncthreads();
    for (int st = 128; st > 0; st >>= 1) {
        if (tid < st) red[tid] += red[tid + st];
        __syncthreads();
    }
    if (tid == 0 && out_size > LOSS_OFF)
        dout[LOSS_OFF] = (float)(1.25 * red[0] / (8.0 * 33554432.0));
}

// ---------------------------------------------------------------- launch
extern "C" void kernel_launch(void* const* d_in, const int* in_sizes, int n_in,
                              void* d_out, int out_size) {
    const float* xin = (const float*)d_in[0];
    const float* cb  = (const float*)d_in[1];
    if (n_in >= 2 && in_sizes[0] == CBELEMS) {
        xin = (const float*)d_in[1];
        cb  = (const float*)d_in[0];
    }
    float* dout = (float*)d_out;
    unsigned long long osz = (unsigned long long)out_size;

    static bool attr_set = false;
    if (!attr_set) {
        cudaFuncSetAttribute(rvq_kernel, cudaFuncAttributeMaxDynamicSharedMemorySize,
                             SMEM_TOT);
        attr_set = true;
    }

    e2_kernel<<<(LL * GG * KK + 255) / 256, 256>>>(cb);
    split_e_kernel<<<(CBELEMS + 255) / 256, 256>>>(cb);
    dim3 grid(512, GG);
    rvq_kernel<<<grid, NTH, SMEM_TOT>>>(xin, cb, dout, osz);
    loss_kernel<<<1, 256>>>(dout, osz);
}

// round 13
// speedup vs baseline: 1.7962x; 1.0825x over previous
#include <cuda_runtime.h>
#include <cuda_bf16.h>

// Residual VQ (L=8, G=2, K=1024, D=256), B=16, T=4096, N=65536.
// bf16 split MMA (xh*eh + xh*el + xl*eh, fp32 accum) -> approx distances;
// sound margin -> <=3 candidates -> exact fp32 reference-semantics rescore.
// Round 13: round 12 (512 threads / 16 warps, cross-kb B prefetch) with the
// cp.async bounds bug fixed (1024 vectors per chunk, not 2048).

#define LL 8
#define GG 2
#define KK 1024
#define DD 256
#define TT 4096
#define NTOK 65536ull
#define TILE 128
#define NTH 512
#define APITCH 264      // bf16 per A row (256 + 8 pad) -> 528B
#define BPITCH 72       // bf16 per B row (64 + 8 pad)  -> 144B
#define BSTAGE 18432    // 128 codes * BPITCH * 2B (one split, one stage)

#define QOUT_ELEMS 33554432ull
#define LOSS_OFF   33554432ull
#define IDX_OFF    33554433ull

#define CBELEMS (LL * GG * KK * DD)
#define NCTA 1024

// smem byte offsets
#define OFF_AH   0          // bf16 [128][264]  67584
#define OFF_AL   67584      // bf16 [128][264]  67584
#define OFF_B    135168     // 2 stages x (H 18432 + L 18432) = 73728
#define OFF_E2S  208896     // fp32 [128]
#define OFF_ASM  209408     // fp32 [128]
#define OFF_PV   209920     // fp32 [128][8]
#define OFF_PI   214016     // int  [128][8]
#define OFF_RUNI 218112     // int  [128]
#define OFF_RED  218624     // double [512]
#define SMEM_TOT 222720

__device__ float          g_e2[LL * GG * KK];
__device__ double         g_loss[NCTA];
__device__ __nv_bfloat16  g_ehi[CBELEMS];
__device__ __nv_bfloat16  g_elo[CBELEMS];
__device__ float          g_X[(size_t)NCTA * DD * TILE];   // per-CTA residual [d][t]

// ---------------------------------------------------------------- asm helpers
__device__ __forceinline__ void mma16816(float* c, const unsigned* a, const unsigned* b) {
    asm volatile(
        "mma.sync.aligned.m16n8k16.row.col.f32.bf16.bf16.f32 "
        "{%0,%1,%2,%3},{%4,%5,%6,%7},{%8,%9},{%0,%1,%2,%3};"
        : "+f"(c[0]), "+f"(c[1]), "+f"(c[2]), "+f"(c[3])
        : "r"(a[0]), "r"(a[1]), "r"(a[2]), "r"(a[3]), "r"(b[0]), "r"(b[1]));
}
__device__ __forceinline__ void ldsm_x4(unsigned* r, unsigned addr) {
    asm volatile("ldmatrix.sync.aligned.m8n8.x4.shared.b16 {%0,%1,%2,%3},[%4];"
                 : "=r"(r[0]), "=r"(r[1]), "=r"(r[2]), "=r"(r[3]) : "r"(addr));
}
__device__ __forceinline__ void ldsm_x2(unsigned* r, unsigned addr) {
    asm volatile("ldmatrix.sync.aligned.m8n8.x2.shared.b16 {%0,%1},[%2];"
                 : "=r"(r[0]), "=r"(r[1]) : "r"(addr));
}
__device__ __forceinline__ void cpasync16(unsigned dst, const void* src) {
    asm volatile("cp.async.cg.shared.global [%0], [%1], 16;"
                 :: "r"(dst), "l"(__cvta_generic_to_global(src)));
}
__device__ __forceinline__ void merge2(float& v1, int& i1, float& v2, int& i2,
                                       float w1, int j1, float w2, int j2) {
    if (w1 < v1) {
        float t2 = v1; int ti2 = i1;
        v1 = w1; i1 = j1;
        if (w2 < t2) { v2 = w2; i2 = j2; } else { v2 = t2; i2 = ti2; }
    } else if (w1 < v2) {
        v2 = w1; i2 = j1;
    }
}

// ---------------------------------------------------------------- ||e||^2 (exact ref rounding)
__global__ void e2_kernel(const float* __restrict__ cb) {
    int c = blockIdx.x * blockDim.x + threadIdx.x;
    if (c >= LL * GG * KK) return;
    const float* e = cb + (size_t)c * DD;
    float s = 0.0f;
    for (int d = 0; d < DD; ++d) {
        float v = e[d];
        s = __fadd_rn(s, __fmul_rn(v, v));
    }
    g_e2[c] = s;
}

// ---------------------------------------------------------------- codebook bf16 split
__global__ void split_e_kernel(const float* __restrict__ cb) {
    int i = blockIdx.x * blockDim.x + threadIdx.x;
    if (i >= CBELEMS) return;
    float v = cb[i];
    __nv_bfloat16 h = __float2bfloat16_rn(v);
    float r = __fsub_rn(v, __bfloat162float(h));
    g_ehi[i] = h;
    g_elo[i] = __float2bfloat16_rn(r);
}

// ---------------------------------------------------------------- main
__global__ void __launch_bounds__(NTH, 1)
rvq_kernel(const float* __restrict__ xin, const float* __restrict__ cb,
           float* __restrict__ dout, unsigned long long out_size) {
    extern __shared__ char smraw[];
    __nv_bfloat16*  Ah   = (__nv_bfloat16*)(smraw + OFF_AH);
    __nv_bfloat16*  Al   = (__nv_bfloat16*)(smraw + OFF_AL);
    float*          E2s  = (float*)(smraw + OFF_E2S);
    float*          Asm  = (float*)(smraw + OFF_ASM);
    float*          PV   = (float*)(smraw + OFF_PV);
    int*            PI   = (int*)(smraw + OFF_PI);
    int*            RUNI = (int*)(smraw + OFF_RUNI);
    double*         red  = (double*)(smraw + OFF_RED);

    const unsigned smbase = (unsigned)__cvta_generic_to_shared(smraw);
    const unsigned uBH[2] = {smbase + OFF_B, smbase + OFF_B + 2 * BSTAGE};

    const int tid  = threadIdx.x;
    const int lane = tid & 31;
    const int warp = tid >> 5;
    const int wm   = warp >> 2;           // 0..3  (32 token rows each)
    const int wn   = warp & 3;            // 0..3  (32 code cols)
    const int r4   = lane >> 2;           // 0..7
    const int kq   = lane & 3;            // 0..3

    // ldmatrix lane address components (mapping verified rounds 7/9/10/11)
    const int lrowA  = (lane & 7) + (((lane >> 3) & 1) << 3);
    const int lkoffA = (lane >> 4) << 3;
    const unsigned aBaseH = smbase + OFF_AH +
        (unsigned)(((wm * 32 + lrowA) * APITCH + lkoffA) << 1);
    const unsigned aBaseL = smbase + OFF_AL +
        (unsigned)(((wm * 32 + lrowA) * APITCH + lkoffA) << 1);
    const int rB   = lane & 7;
    const int selB = (lane >> 3) & 1;
    const unsigned bLaneOff = (unsigned)(((wn * 32 + rB) * BPITCH + selB * 8) << 1);

    const int g    = blockIdx.y;
    const int tile = blockIdx.x;              // 0..511
    const int b    = tile >> 5;               // 32 tiles of 128 per batch row
    const int t0   = (tile & 31) << 7;
    const int cta  = g * 512 + tile;
    const float* xb = xin + ((size_t)b * (GG * DD) + (size_t)g * DD) * TT + t0;
    float* gX = g_X + (size_t)cta * (DD * TILE);

    // residual := xin tile, [d][t] in global scratch (both sides coalesced)
    for (int i = tid; i < DD * TILE; i += NTH) {
        int d = i >> 7, t = i & 127;
        gX[i] = xb[(size_t)d * TT + t];
    }
    __syncthreads();

    double lacc = 0.0;

    for (int l = 0; l < LL; ++l) {
        const int    cbase = (l * GG + g) * KK;
        const float* cbl   = cb + (size_t)cbase * DD;

        // exact a_n = sequential fl(x^2) sum, d ascending (ref reduce order)
        if (tid < TILE) {
            float s = 0.0f;
            const float* xc = gX + tid;
#pragma unroll 8
            for (int d = 0; d < DD; ++d) {
                float v = xc[d * TILE];
                s = __fadd_rn(s, __fmul_rn(v, v));
            }
            Asm[tid] = s;
        }
        // split residual into A_hi/A_lo bf16 [token][d]
        for (int i = tid; i < DD * TILE; i += NTH) {
            int d = i >> 7, t = i & 127;
            float v = gX[i];
            __nv_bfloat16 h = __float2bfloat16_rn(v);
            float rlo = __fsub_rn(v, __bfloat162float(h));
            Ah[t * APITCH + d] = h;
            Al[t * APITCH + d] = __float2bfloat16_rn(rlo);
        }
        __syncthreads();

        // per-token running top-3 (registers, tid<128)
        float t3v0 = 3.0e38f, t3v1 = 3.0e38f, t3v2 = 3.0e38f;
        int   t3i0 = 0,       t3i1 = 0,       t3i2 = 0;

        // prefetch kb=0 chunk 0 into stage 0 (1024 16B-vectors per split)
        {
            const size_t gb0 = ((size_t)cbase) * DD;
            const __nv_bfloat16* sH = g_ehi + gb0;
            const __nv_bfloat16* sL = g_elo + gb0;
#pragma unroll
            for (int it = 0; it < 2; ++it) {
                int v = tid + it * NTH;               // 0..1023
                int code = v >> 3, d8 = (v & 7) * 8;
                unsigned doff = (unsigned)((code * BPITCH + d8) << 1);
                cpasync16(uBH[0] + doff, sH + (size_t)code * DD + d8);
                cpasync16(uBH[0] + BSTAGE + doff, sL + (size_t)code * DD + d8);
            }
            asm volatile("cp.async.commit_group;");
        }

        for (int kb = 0; kb < 8; ++kb) {               // 8 blocks of 128 codes
            const size_t gbBlk = ((size_t)(cbase + kb * 128)) * DD;
            if (tid < 128) E2s[tid] = g_e2[cbase + kb * 128 + tid];

            float acc[2][4][4];
#pragma unroll
            for (int mt = 0; mt < 2; ++mt)
#pragma unroll
                for (int nt = 0; nt < 4; ++nt)
#pragma unroll
                    for (int e = 0; e < 4; ++e) acc[mt][nt][e] = 0.f;

#pragma unroll 1
            for (int kc = 0; kc < 4; ++kc) {           // 4 d-chunks of 64
                if (kc < 3) {                          // prefetch next chunk
                    const __nv_bfloat16* sH = g_ehi + gbBlk + (kc + 1) * 64;
                    const __nv_bfloat16* sL = g_elo + gbBlk + (kc + 1) * 64;
                    unsigned dh = uBH[(kc + 1) & 1];
#pragma unroll
                    for (int it = 0; it < 2; ++it) {
                        int v = tid + it * NTH;       // 0..1023
                        int code = v >> 3, d8 = (v & 7) * 8;
                        unsigned doff = (unsigned)((code * BPITCH + d8) << 1);
                        cpasync16(dh + doff, sH + (size_t)code * DD + d8);
                        cpasync16(dh + BSTAGE + doff, sL + (size_t)code * DD + d8);
                    }
                    asm volatile("cp.async.commit_group;");
                    asm volatile("cp.async.wait_group 1;");
                } else {
                    asm volatile("cp.async.wait_group 0;");
                }
                __syncthreads();

                const unsigned bh_st = uBH[kc & 1] + bLaneOff;
                const unsigned bl_st = bh_st + BSTAGE;
#pragma unroll
                for (int ks = 0; ks < 4; ++ks) {       // k16 steps
                    const unsigned akoff = (unsigned)((kc * 64 + ks * 16) << 1);
                    const unsigned bkoff = (unsigned)((ks * 16) << 1);
                    unsigned ah[2][4], al[2][4], bh[4][2], bl[4][2];
#pragma unroll
                    for (int mt = 0; mt < 2; ++mt) {
                        ldsm_x4(ah[mt], aBaseH + (unsigned)(mt * 16 * APITCH * 2) + akoff);
                        ldsm_x4(al[mt], aBaseL + (unsigned)(mt * 16 * APITCH * 2) + akoff);
                    }
#pragma unroll
                    for (int nt = 0; nt < 4; ++nt) {
                        ldsm_x2(bh[nt], bh_st + (unsigned)(nt * 8 * BPITCH * 2) + bkoff);
                        ldsm_x2(bl[nt], bl_st + (unsigned)(nt * 8 * BPITCH * 2) + bkoff);
                    }
#pragma unroll
                    for (int mt = 0; mt < 2; ++mt)
#pragma unroll
                        for (int nt = 0; nt < 4; ++nt) {
                            mma16816(acc[mt][nt], ah[mt], bh[nt]);
                            mma16816(acc[mt][nt], ah[mt], bl[nt]);
                            mma16816(acc[mt][nt], al[mt], bh[nt]);
                        }
                }
                __syncthreads();
            }

            // cross-kb prefetch: issue next block's chunk 0 (stage 0) now,
            // so its latency hides under the epilogue + merge below.
            if (kb < 7) {
                const size_t gbN = ((size_t)(cbase + (kb + 1) * 128)) * DD;
                const __nv_bfloat16* sH = g_ehi + gbN;
                const __nv_bfloat16* sL = g_elo + gbN;
#pragma unroll
                for (int it = 0; it < 2; ++it) {
                    int v = tid + it * NTH;           // 0..1023
                    int code = v >> 3, d8 = (v & 7) * 8;
                    unsigned doff = (unsigned)((code * BPITCH + d8) << 1);
                    cpasync16(uBH[0] + doff, sH + (size_t)code * DD + d8);
                    cpasync16(uBH[0] + BSTAGE + doff, sL + (size_t)code * DD + d8);
                }
                asm volatile("cp.async.commit_group;");
            }

            // epilogue: distances + per-warp per-row top2
#pragma unroll
            for (int mt = 0; mt < 2; ++mt)
#pragma unroll
                for (int h = 0; h < 2; ++h) {
                    int row = wm * 32 + mt * 16 + h * 8 + r4;
                    float a_tok = Asm[row];
                    float w1 = 3.0e38f, w2 = 3.0e38f; int j1 = 0, j2 = 0;
#pragma unroll
                    for (int nt = 0; nt < 4; ++nt)
#pragma unroll
                        for (int j = 0; j < 2; ++j) {
                            int colq = wn * 32 + nt * 8 + 2 * kq + j;
                            float c = acc[mt][nt][h * 2 + j];
                            float dv = __fadd_rn(__fadd_rn(a_tok, E2s[colq]),
                                                 __fmul_rn(-2.0f, c));
                            int idx = kb * 128 + colq;
                            if (dv < w1) { w2 = w1; j2 = j1; w1 = dv; j1 = idx; }
                            else if (dv < w2) { w2 = dv; j2 = idx; }
                        }
#pragma unroll
                    for (int s = 1; s <= 2; s <<= 1) {
                        float u1 = __shfl_xor_sync(0xffffffffu, w1, s);
                        int   k1 = __shfl_xor_sync(0xffffffffu, j1, s);
                        float u2 = __shfl_xor_sync(0xffffffffu, w2, s);
                        int   k2 = __shfl_xor_sync(0xffffffffu, j2, s);
                        merge2(w1, j1, w2, j2, u1, k1, u2, k2);
                    }
                    if (kq == 0) {
                        PV[row * 8 + wn * 2 + 0] = w1;  PI[row * 8 + wn * 2 + 0] = j1;
                        PV[row * 8 + wn * 2 + 1] = w2;  PI[row * 8 + wn * 2 + 1] = j2;
                    }
                }
            __syncthreads();
            if (tid < TILE) {                          // merge 8 partials into top3
#pragma unroll
                for (int e = 0; e < 8; ++e) {
                    float v = PV[tid * 8 + e]; int i = PI[tid * 8 + e];
                    if (v < t3v0) { t3v2 = t3v1; t3i2 = t3i1; t3v1 = t3v0; t3i1 = t3i0;
                                    t3v0 = v; t3i0 = i; }
                    else if (v < t3v1) { t3v2 = t3v1; t3i2 = t3i1; t3v1 = v; t3i1 = i; }
                    else if (v < t3v2) { t3v2 = v; t3i2 = i; }
                }
            }
            __syncthreads();
        }

        // finalize winner: sound margin; exact re-score for ambiguous tokens
        if (tid < TILE) {
            float a_tok  = Asm[tid];
            float margin = __fmaf_rn(a_tok, 2.4e-7f, 1.0e-5f);
            int winner = t3i0;
            if (t3v1 <= t3v0 + margin) {
                int ci[3]; int nc = 0;
                ci[nc++] = t3i0;
                ci[nc++] = t3i1;
                if (t3v2 <= t3v0 + margin) ci[nc++] = t3i2;
                if (nc == 3) {
                    int a0 = ci[0], a1 = ci[1], a2 = ci[2], t;
                    if (a1 < a0) { t = a0; a0 = a1; a1 = t; }
                    if (a2 < a1) { t = a1; a1 = a2; a2 = t; }
                    if (a1 < a0) { t = a0; a0 = a1; a1 = t; }
                    ci[0] = a0; ci[1] = a1; ci[2] = a2;
                } else if (ci[1] < ci[0]) { int t = ci[0]; ci[0] = ci[1]; ci[1] = t; }
                float best = 3.0e38f; winner = ci[0];
                for (int cc = 0; cc < nc; ++cc) {
                    int code = ci[cc];
                    const float* ev = cbl + (size_t)code * DD;
                    const float* xc = gX + tid;
                    float c = 0.0f;
#pragma unroll 8
                    for (int d = 0; d < DD; ++d)
                        c = __fmaf_rn(xc[d * TILE], ev[d], c);
                    float dv = __fadd_rn(__fadd_rn(a_tok, g_e2[cbase + code]),
                                         __fmul_rn(-2.0f, c));
                    if (dv < best) { best = dv; winner = code; }
                }
            }
            RUNI[tid] = winner;
            if (out_size > IDX_OFF) {
                size_t n = (size_t)b * TT + t0 + tid;
                size_t o = IDX_OFF + ((size_t)(l * GG + g)) * NTOK + n;
                if (o < out_size) dout[o] = (float)winner;
            }
        }
        __syncthreads();

        // residual update (reference STE elementwise):
        //   delta = fl(zq - x); quant = fl(x + delta); x' = fl(x - quant)
        {
            int token = tid >> 2, dq = tid & 3;
            int code  = RUNI[token];
            const float* ev = cbl + (size_t)code * DD + dq * 64;
            float* xc = gX + (dq * 64) * TILE + token;
#pragma unroll 8
            for (int dd = 0; dd < 64; ++dd) {
                float x  = xc[dd * TILE];
                float dl = __fsub_rn(ev[dd], x);
                float qn = __fadd_rn(x, dl);
                xc[dd * TILE] = __fsub_rn(x, qn);
                lacc += (double)dl * (double)dl;
            }
        }
        __syncthreads();
    }

    // quantized_out = xin - final residual
    for (int i = tid; i < DD * TILE; i += NTH) {
        int d = i >> 7, t = i & 127;
        size_t o = ((size_t)b * (GG * DD) + (size_t)g * DD + d) * TT + t0 + t;
        if (o < out_size && o < QOUT_ELEMS)
            dout[o] = __fsub_rn(xb[(size_t)d * TT + t], gX[i]);
    }

    // deterministic per-CTA loss partial
    red[tid] = lacc;
    __syncthreads();
    for (int s = 256; s > 0; s >>= 1) {
        if (tid < s) red[tid] += red[tid + s];
        __syncthreads();
    }
    if (tid == 0) g_loss[cta] = red[0];
}

// ---------------------------------------------------------------- loss reduce
__global__ void loss_kernel(float* __restrict__ dout, unsigned long long out_size) {
    __shared__ double red[256];
    int tid = threadIdx.x;
    double s = 0.0;
    for (int i = tid; i < NCTA; i += 256) s += g_loss[i];
    red[tid] = s;
    __syncthreads();
    for (int st = 128; st > 0; st >>= 1) {
        if (tid < st) red[tid] += red[tid + st];
        __syncthreads();
    }
    if (tid == 0 && out_size > LOSS_OFF)
        dout[LOSS_OFF] = (float)(1.25 * red[0] / (8.0 * 33554432.0));
}

// ---------------------------------------------------------------- launch
extern "C" void kernel_launch(void* const* d_in, const int* in_sizes, int n_in,
                              void* d_out, int out_size) {
    const float* xin = (const float*)d_in[0];
    const float* cb  = (const float*)d_in[1];
    if (n_in >= 2 && in_sizes[0] == CBELEMS) {
        xin = (const float*)d_in[1];
        cb  = (const float*)d_in[0];
    }
    float* dout = (float*)d_out;
    unsigned long long osz = (unsigned long long)out_size;

    static bool attr_set = false;
    if (!attr_set) {
        cudaFuncSetAttribute(rvq_kernel, cudaFuncAttributeMaxDynamicSharedMemorySize,
                             SMEM_TOT);
        attr_set = true;
    }

    e2_kernel<<<(LL * GG * KK + 255) / 256, 256>>>(cb);
    split_e_kernel<<<(CBELEMS + 255) / 256, 256>>>(cb);
    dim3 grid(512, GG);
    rvq_kernel<<<grid, NTH, SMEM_TOT>>>(xin, cb, dout, osz);
    loss_kernel<<<1, 256>>>(dout, osz);
}

// round 15
// speedup vs baseline: 2.1055x; 1.1722x over previous
#include <cuda_runtime.h>
#include <cuda_fp16.h>

// Residual VQ (L=8, G=2, K=1024, D=256), B=16, T=4096, N=65536.
// fp16 2-term split MMA: x = Ah + Al (both fp16), e -> Eh = fl16(1024*e);
// c~ = (Ah+Al)*Eh accumulated fp32, distance d~ = fl(fl(a+b) - 2*c~/1024).
// Error sigma ~2e-6 << margin (a*2.4e-7+1e-5); same sound-margin -> <=3
// candidate -> exact fp32 reference-semantics rescue as rounds 6-13.
// Skeleton = round 13 (512 thr / 16 warps, cp.async double buffer + cross-kb
// prefetch, ldmatrix, shuffle top-2 epilogue, global-scratch residual).

#define LL 8
#define GG 2
#define KK 1024
#define DD 256
#define TT 4096
#define NTOK 65536ull
#define TILE 128
#define NTH 512
#define APITCH 264      // fp16 per A row (256 + 8 pad) -> 528B
#define BPITCH 72       // fp16 per B row (64 + 8 pad)  -> 144B
#define BSTAGE 18432    // 128 codes * BPITCH * 2B (one stage)

#define QOUT_ELEMS 33554432ull
#define LOSS_OFF   33554432ull
#define IDX_OFF    33554433ull

#define CBELEMS (LL * GG * KK * DD)
#define NCTA 1024

// smem byte offsets
#define OFF_AH   0          // fp16 [128][264]  67584
#define OFF_AL   67584      // fp16 [128][264]  67584
#define OFF_B    135168     // 2 stages x 18432 = 36864
#define OFF_E2S  172032     // fp32 [128]
#define OFF_ASM  172544     // fp32 [128]
#define OFF_PV   173056     // fp32 [128][8]
#define OFF_PI   177152     // int  [128][8]
#define OFF_RUNI 181248     // int  [128]
#define OFF_RED  181760     // double [512]
#define SMEM_TOT 185856

__device__ float   g_e2[LL * GG * KK];
__device__ double  g_loss[NCTA];
__device__ __half  g_eh[CBELEMS];                          // fl16(1024 * e)
__device__ float   g_X[(size_t)NCTA * DD * TILE];          // per-CTA residual [d][t]

// ---------------------------------------------------------------- asm helpers
__device__ __forceinline__ void mma16816h(float* c, const unsigned* a, const unsigned* b) {
    asm volatile(
        "mma.sync.aligned.m16n8k16.row.col.f32.f16.f16.f32 "
        "{%0,%1,%2,%3},{%4,%5,%6,%7},{%8,%9},{%0,%1,%2,%3};"
        : "+f"(c[0]), "+f"(c[1]), "+f"(c[2]), "+f"(c[3])
        : "r"(a[0]), "r"(a[1]), "r"(a[2]), "r"(a[3]), "r"(b[0]), "r"(b[1]));
}
__device__ __forceinline__ void ldsm_x4(unsigned* r, unsigned addr) {
    asm volatile("ldmatrix.sync.aligned.m8n8.x4.shared.b16 {%0,%1,%2,%3},[%4];"
                 : "=r"(r[0]), "=r"(r[1]), "=r"(r[2]), "=r"(r[3]) : "r"(addr));
}
__device__ __forceinline__ void ldsm_x2(unsigned* r, unsigned addr) {
    asm volatile("ldmatrix.sync.aligned.m8n8.x2.shared.b16 {%0,%1},[%2];"
                 : "=r"(r[0]), "=r"(r[1]) : "r"(addr));
}
__device__ __forceinline__ void cpasync16(unsigned dst, const void* src) {
    asm volatile("cp.async.cg.shared.global [%0], [%1], 16;"
                 :: "r"(dst), "l"(__cvta_generic_to_global(src)));
}
__device__ __forceinline__ void merge2(float& v1, int& i1, float& v2, int& i2,
                                       float w1, int j1, float w2, int j2) {
    if (w1 < v1) {
        float t2 = v1; int ti2 = i1;
        v1 = w1; i1 = j1;
        if (w2 < t2) { v2 = w2; i2 = j2; } else { v2 = t2; i2 = ti2; }
    } else if (w1 < v2) {
        v2 = w1; i2 = j1;
    }
}

// ---------------------------------------------------------------- ||e||^2 (exact ref rounding)
__global__ void e2_kernel(const float* __restrict__ cb) {
    int c = blockIdx.x * blockDim.x + threadIdx.x;
    if (c >= LL * GG * KK) return;
    const float* e = cb + (size_t)c * DD;
    float s = 0.0f;
    for (int d = 0; d < DD; ++d) {
        float v = e[d];
        s = __fadd_rn(s, __fmul_rn(v, v));
    }
    g_e2[c] = s;
}

// ---------------------------------------------------------------- codebook fp16 (scaled 1024x)
__global__ void eh_kernel(const float* __restrict__ cb) {
    int i = blockIdx.x * blockDim.x + threadIdx.x;
    if (i >= CBELEMS) return;
    g_eh[i] = __float2half_rn(__fmul_rn(cb[i], 1024.0f));
}

// ---------------------------------------------------------------- main
__global__ void __launch_bounds__(NTH, 1)
rvq_kernel(const float* __restrict__ xin, const float* __restrict__ cb,
           float* __restrict__ dout, unsigned long long out_size) {
    extern __shared__ char smraw[];
    __half*  Ah   = (__half*)(smraw + OFF_AH);
    __half*  Al   = (__half*)(smraw + OFF_AL);
    float*   E2s  = (float*)(smraw + OFF_E2S);
    float*   Asm  = (float*)(smraw + OFF_ASM);
    float*   PV   = (float*)(smraw + OFF_PV);
    int*     PI   = (int*)(smraw + OFF_PI);
    int*     RUNI = (int*)(smraw + OFF_RUNI);
    double*  red  = (double*)(smraw + OFF_RED);

    const unsigned smbase = (unsigned)__cvta_generic_to_shared(smraw);
    const unsigned uB[2] = {smbase + OFF_B, smbase + OFF_B + BSTAGE};

    const int tid  = threadIdx.x;
    const int lane = tid & 31;
    const int warp = tid >> 5;
    const int wm   = warp >> 2;           // 0..3  (32 token rows each)
    const int wn   = warp & 3;            // 0..3  (32 code cols)
    const int r4   = lane >> 2;           // 0..7
    const int kq   = lane & 3;            // 0..3

    // ldmatrix lane address components (mapping verified rounds 7-13)
    const int lrowA  = (lane & 7) + (((lane >> 3) & 1) << 3);
    const int lkoffA = (lane >> 4) << 3;
    const unsigned aBaseH = smbase + OFF_AH +
        (unsigned)(((wm * 32 + lrowA) * APITCH + lkoffA) << 1);
    const unsigned aBaseL = smbase + OFF_AL +
        (unsigned)(((wm * 32 + lrowA) * APITCH + lkoffA) << 1);
    const int rB   = lane & 7;
    const int selB = (lane >> 3) & 1;
    const unsigned bLaneOff = (unsigned)(((wn * 32 + rB) * BPITCH + selB * 8) << 1);

    const int g    = blockIdx.y;
    const int tile = blockIdx.x;              // 0..511
    const int b    = tile >> 5;
    const int t0   = (tile & 31) << 7;
    const int cta  = g * 512 + tile;
    const float* xb = xin + ((size_t)b * (GG * DD) + (size_t)g * DD) * TT + t0;
    float* gX = g_X + (size_t)cta * (DD * TILE);

    // residual := xin tile, [d][t] in global scratch
    for (int i = tid; i < DD * TILE; i += NTH) {
        int d = i >> 7, t = i & 127;
        gX[i] = xb[(size_t)d * TT + t];
    }
    __syncthreads();

    double lacc = 0.0;

    for (int l = 0; l < LL; ++l) {
        const int    cbase = (l * GG + g) * KK;
        const float* cbl   = cb + (size_t)cbase * DD;

        // exact a_n = sequential fl(x^2) sum, d ascending (ref reduce order)
        if (tid < TILE) {
            float s = 0.0f;
            const float* xc = gX + tid;
#pragma unroll 8
            for (int d = 0; d < DD; ++d) {
                float v = xc[d * TILE];
                s = __fadd_rn(s, __fmul_rn(v, v));
            }
            Asm[tid] = s;
        }
        // split residual into fp16 Ah + Al (x to ~22 bits)
        for (int i = tid; i < DD * TILE; i += NTH) {
            int d = i >> 7, t = i & 127;
            float v = gX[i];
            __half h = __float2half_rn(v);
            float rlo = __fsub_rn(v, __half2float(h));
            Ah[t * APITCH + d] = h;
            Al[t * APITCH + d] = __float2half_rn(rlo);
        }
        __syncthreads();

        // per-token running top-3 (registers, tid<128)
        float t3v0 = 3.0e38f, t3v1 = 3.0e38f, t3v2 = 3.0e38f;
        int   t3i0 = 0,       t3i1 = 0,       t3i2 = 0;

        // prefetch kb=0 chunk 0 into stage 0 (1024 16B vectors)
        {
            const __half* sH = g_eh + ((size_t)cbase) * DD;
#pragma unroll
            for (int it = 0; it < 2; ++it) {
                int v = tid + it * NTH;               // 0..1023
                int code = v >> 3, d8 = (v & 7) * 8;
                cpasync16(uB[0] + (unsigned)((code * BPITCH + d8) << 1),
                          sH + (size_t)code * DD + d8);
            }
            asm volatile("cp.async.commit_group;");
        }

        for (int kb = 0; kb < 8; ++kb) {               // 8 blocks of 128 codes
            const size_t gbBlk = ((size_t)(cbase + kb * 128)) * DD;
            if (tid < 128) E2s[tid] = g_e2[cbase + kb * 128 + tid];

            float acc[2][4][4];
#pragma unroll
            for (int mt = 0; mt < 2; ++mt)
#pragma unroll
                for (int nt = 0; nt < 4; ++nt)
#pragma unroll
                    for (int e = 0; e < 4; ++e) acc[mt][nt][e] = 0.f;

#pragma unroll 1
            for (int kc = 0; kc < 4; ++kc) {           // 4 d-chunks of 64
                if (kc < 3) {                          // prefetch next chunk
                    const __half* sH = g_eh + gbBlk + (kc + 1) * 64;
                    unsigned dh = uB[(kc + 1) & 1];
#pragma unroll
                    for (int it = 0; it < 2; ++it) {
                        int v = tid + it * NTH;       // 0..1023
                        int code = v >> 3, d8 = (v & 7) * 8;
                        cpasync16(dh + (unsigned)((code * BPITCH + d8) << 1),
                                  sH + (size_t)code * DD + d8);
                    }
                    asm volatile("cp.async.commit_group;");
                    asm volatile("cp.async.wait_group 1;");
                } else {
                    asm volatile("cp.async.wait_group 0;");
                }
                __syncthreads();

                const unsigned b_st = uB[kc & 1] + bLaneOff;
#pragma unroll
                for (int ks = 0; ks < 4; ++ks) {       // k16 steps
                    const unsigned akoff = (unsigned)((kc * 64 + ks * 16) << 1);
                    const unsigned bkoff = (unsigned)((ks * 16) << 1);
                    unsigned ah[2][4], al[2][4], bh[4][2];
#pragma unroll
                    for (int mt = 0; mt < 2; ++mt) {
                        ldsm_x4(ah[mt], aBaseH + (unsigned)(mt * 16 * APITCH * 2) + akoff);
                        ldsm_x4(al[mt], aBaseL + (unsigned)(mt * 16 * APITCH * 2) + akoff);
                    }
#pragma unroll
                    for (int nt = 0; nt < 4; ++nt)
                        ldsm_x2(bh[nt], b_st + (unsigned)(nt * 8 * BPITCH * 2) + bkoff);
#pragma unroll
                    for (int mt = 0; mt < 2; ++mt)
#pragma unroll
                        for (int nt = 0; nt < 4; ++nt) {
                            mma16816h(acc[mt][nt], ah[mt], bh[nt]);
                            mma16816h(acc[mt][nt], al[mt], bh[nt]);
                        }
                }
                __syncthreads();
            }

            // cross-kb prefetch of next block's chunk 0 into stage 0
            if (kb < 7) {
                const __half* sH = g_eh + ((size_t)(cbase + (kb + 1) * 128)) * DD;
#pragma unroll
                for (int it = 0; it < 2; ++it) {
                    int v = tid + it * NTH;           // 0..1023
                    int code = v >> 3, d8 = (v & 7) * 8;
                    cpasync16(uB[0] + (unsigned)((code * BPITCH + d8) << 1),
                              sH + (size_t)code * DD + d8);
                }
                asm volatile("cp.async.commit_group;");
            }

            // epilogue: distances + per-warp per-row top2
#pragma unroll
            for (int mt = 0; mt < 2; ++mt)
#pragma unroll
                for (int h = 0; h < 2; ++h) {
                    int row = wm * 32 + mt * 16 + h * 8 + r4;
                    float a_tok = Asm[row];
                    float w1 = 3.0e38f, w2 = 3.0e38f; int j1 = 0, j2 = 0;
#pragma unroll
                    for (int nt = 0; nt < 4; ++nt)
#pragma unroll
                        for (int j = 0; j < 2; ++j) {
                            int colq = wn * 32 + nt * 8 + 2 * kq + j;
                            float c = acc[mt][nt][h * 2 + j];
                            // d~ = fl( fl(a+b) - 2*(c~/1024) ), scale exact
                            float dv = __fadd_rn(__fadd_rn(a_tok, E2s[colq]),
                                                 __fmul_rn(c, -0.001953125f));
                            int idx = kb * 128 + colq;
                            if (dv < w1) { w2 = w1; j2 = j1; w1 = dv; j1 = idx; }
                            else if (dv < w2) { w2 = dv; j2 = idx; }
                        }
#pragma unroll
                    for (int s = 1; s <= 2; s <<= 1) {
                        float u1 = __shfl_xor_sync(0xffffffffu, w1, s);
                        int   k1 = __shfl_xor_sync(0xffffffffu, j1, s);
                        float u2 = __shfl_xor_sync(0xffffffffu, w2, s);
                        int   k2 = __shfl_xor_sync(0xffffffffu, j2, s);
                        mer2:
                        merge2(w1, j1, w2, j2, u1, k1, u2, k2);
                    }
                    if (kq == 0) {
                        PV[row * 8 + wn * 2 + 0] = w1;  PI[row * 8 + wn * 2 + 0] = j1;
                        PV[row * 8 + wn * 2 + 1] = w2;  PI[row * 8 + wn * 2 + 1] = j2;
                    }
                }
            __syncthreads();
            if (tid < TILE) {                          // merge 8 partials into top3
#pragma unroll
                for (int e = 0; e < 8; ++e) {
                    float v = PV[tid * 8 + e]; int i = PI[tid * 8 + e];
                    if (v < t3v0) { t3v2 = t3v1; t3i2 = t3i1; t3v1 = t3v0; t3i1 = t3i0;
                                    t3v0 = v; t3i0 = i; }
                    else if (v < t3v1) { t3v2 = t3v1; t3i2 = t3i1; t3v1 = v; t3i1 = i; }
                    else if (v < t3v2) { t3v2 = v; t3i2 = i; }
                }
            }
            __syncthreads();
        }

        // finalize winner: sound margin; exact re-score for ambiguous tokens
        if (tid < TILE) {
            float a_tok  = Asm[tid];
            float margin = __fmaf_rn(a_tok, 2.4e-7f, 1.0e-5f);
            int winner = t3i0;
            if (t3v1 <= t3v0 + margin) {
                int ci[3]; int nc = 0;
                ci[nc++] = t3i0;
                ci[nc++] = t3i1;
                if (t3v2 <= t3v0 + margin) ci[nc++] = t3i2;
                if (nc == 3) {
                    int a0 = ci[0], a1 = ci[1], a2 = ci[2], t;
                    if (a1 < a0) { t = a0; a0 = a1; a1 = t; }
                    if (a2 < a1) { t = a1; a1 = a2; a2 = t; }
                    if (a1 < a0) { t = a0; a0 = a1; a1 = t; }
                    ci[0] = a0; ci[1] = a1; ci[2] = a2;
                } else if (ci[1] < ci[0]) { int t = ci[0]; ci[0] = ci[1]; ci[1] = t; }
                float best = 3.0e38f; winner = ci[0];
                for (int cc = 0; cc < nc; ++cc) {
                    int code = ci[cc];
                    const float* ev = cbl + (size_t)code * DD;
                    const float* xc = gX + tid;
                    float c = 0.0f;
#pragma unroll 8
                    for (int d = 0; d < DD; ++d)
                        c = __fmaf_rn(xc[d * TILE], ev[d], c);
                    float dv = __fadd_rn(__fadd_rn(a_tok, g_e2[cbase + code]),
                                         __fmul_rn(-2.0f, c));
                    if (dv < best) { best = dv; winner = code; }
                }
            }
            RUNI[tid] = winner;
            if (out_size > IDX_OFF) {
                size_t n = (size_t)b * TT + t0 + tid;
                size_t o = IDX_OFF + ((size_t)(l * GG + g)) * NTOK + n;
                if (o < out_size) dout[o] = (float)winner;
            }
        }
        __syncthreads();

        // residual update (reference STE elementwise)
        {
            int token = tid >> 2, dq = tid & 3;
            int code  = RUNI[token];
            const float* ev = cbl + (size_t)code * DD + dq * 64;
            float* xc = gX + (dq * 64) * TILE + token;
#pragma unroll 8
            for (int dd = 0; dd < 64; ++dd) {
                float x  = xc[dd * TILE];
                float dl = __fsub_rn(ev[dd], x);
                float qn = __fadd_rn(x, dl);
                xc[dd * TILE] = __fsub_rn(x, qn);
                lacc += (double)dl * (double)dl;
            }
        }
        __syncthreads();
    }

    // quantized_out = xin - final residual
    for (int i = tid; i < DD * TILE; i += NTH) {
        int d = i >> 7, t = i & 127;
        size_t o = ((size_t)b * (GG * DD) + (size_t)g * DD + d) * TT + t0 + t;
        if (o < out_size && o < QOUT_ELEMS)
            dout[o] = __fsub_rn(xb[(size_t)d * TT + t], gX[i]);
    }

    // deterministic per-CTA loss partial
    red[tid] = lacc;
    __syncthreads();
    for (int s = 256; s > 0; s >>= 1) {
        if (tid < s) red[tid] += red[tid + s];
        __syncthreads();
    }
    if (tid == 0) g_loss[cta] = red[0];
}

// ---------------------------------------------------------------- loss reduce
__global__ void loss_kernel(float* __restrict__ dout, unsigned long long out_size) {
    __shared__ double red[256];
    int tid = threadIdx.x;
    double s = 0.0;
    for (int i = tid; i < NCTA; i += 256) s += g_loss[i];
    red[tid] = s;
    __syncthreads();
    for (int st = 128; st > 0; st >>= 1) {
        if (tid < st) red[tid] += red[tid + st];
        __syncthreads();
    }
    if (tid == 0 && out_size > LOSS_OFF)
        dout[LOSS_OFF] = (float)(1.25 * red[0] / (8.0 * 33554432.0));
}

// ---------------------------------------------------------------- launch
extern "C" void kernel_launch(void* const* d_in, const int* in_sizes, int n_in,
                              void* d_out, int out_size) {
    const float* xin = (const float*)d_in[0];
    const float* cb  = (const float*)d_in[1];
    if (n_in >= 2 && in_sizes[0] == CBELEMS) {
        xin = (const float*)d_in[1];
        cb  = (const float*)d_in[0];
    }
    float* dout = (float*)d_out;
    unsigned long long osz = (unsigned long long)out_size;

    static bool attr_set = false;
    if (!attr_set) {
        cudaFuncSetAttribute(rvq_kernel, cudaFuncAttributeMaxDynamicSharedMemorySize,
                             SMEM_TOT);
        attr_set = true;
    }

    e2_kernel<<<(LL * GG * KK + 255) / 256, 256>>>(cb);
    eh_kernel<<<(CBELEMS + 255) / 256, 256>>>(cb);
    dim3 grid(512, GG);
    rvq_kernel<<<grid, NTH, SMEM_TOT>>>(xin, cb, dout, osz);
    loss_kernel<<<1, 256>>>(dout, osz);
}

// round 16
// speedup vs baseline: 2.3132x; 1.0986x over previous
#include <cuda_runtime.h>
#include <cuda_fp16.h>

// Residual VQ (L=8, G=2, K=1024, D=256), B=16, T=4096, N=65536.
// fp16 2-term split MMA: x = Ah + Al (both fp16), e -> Eh = fl16(1024*e);
// c~ = (Ah+Al)*Eh accumulated fp32, d~ = fl(fl(a+b) - 2*c~/1024).
// Sound margin -> <=3 candidates -> exact fp32 reference-semantics rescue.
// Round 16: 256-code blocks (kb 8->4) to halve per-block fixed overhead.

#define LL 8
#define GG 2
#define KK 1024
#define DD 256
#define TT 4096
#define NTOK 65536ull
#define TILE 128
#define NTH 512
#define APITCH 264      // fp16 per A row (256 + 8 pad) -> 528B
#define BPITCH 72       // fp16 per B row (64 + 8 pad)  -> 144B
#define BSTAGE 36864    // 256 codes * BPITCH * 2B (one stage)

#define QOUT_ELEMS 33554432ull
#define LOSS_OFF   33554432ull
#define IDX_OFF    33554433ull

#define CBELEMS (LL * GG * KK * DD)
#define NCTA 1024

// smem byte offsets
#define OFF_AH   0          // fp16 [128][264]  67584
#define OFF_AL   67584      // fp16 [128][264]  67584
#define OFF_B    135168     // 2 stages x 36864 = 73728
#define OFF_E2S  208896     // fp32 [256]
#define OFF_ASM  209920     // fp32 [128]
#define OFF_PV   210432     // fp32 [128][8]
#define OFF_PI   214528     // int  [128][8]
#define OFF_RUNI 218624     // int  [128]
#define OFF_RED  219136     // double [512]
#define SMEM_TOT 223232

__device__ float   g_e2[LL * GG * KK];
__device__ double  g_loss[NCTA];
__device__ __half  g_eh[CBELEMS];                          // fl16(1024 * e)
__device__ float   g_X[(size_t)NCTA * DD * TILE];          // per-CTA residual [d][t]

// ---------------------------------------------------------------- asm helpers
__device__ __forceinline__ void mma16816h(float* c, const unsigned* a, const unsigned* b) {
    asm volatile(
        "mma.sync.aligned.m16n8k16.row.col.f32.f16.f16.f32 "
        "{%0,%1,%2,%3},{%4,%5,%6,%7},{%8,%9},{%0,%1,%2,%3};"
        : "+f"(c[0]), "+f"(c[1]), "+f"(c[2]), "+f"(c[3])
        : "r"(a[0]), "r"(a[1]), "r"(a[2]), "r"(a[3]), "r"(b[0]), "r"(b[1]));
}
__device__ __forceinline__ void ldsm_x4(unsigned* r, unsigned addr) {
    asm volatile("ldmatrix.sync.aligned.m8n8.x4.shared.b16 {%0,%1,%2,%3},[%4];"
                 : "=r"(r[0]), "=r"(r[1]), "=r"(r[2]), "=r"(r[3]) : "r"(addr));
}
__device__ __forceinline__ void ldsm_x2(unsigned* r, unsigned addr) {
    asm volatile("ldmatrix.sync.aligned.m8n8.x2.shared.b16 {%0,%1},[%2];"
                 : "=r"(r[0]), "=r"(r[1]) : "r"(addr));
}
__device__ __forceinline__ void cpasync16(unsigned dst, const void* src) {
    asm volatile("cp.async.cg.shared.global [%0], [%1], 16;"
                 :: "r"(dst), "l"(__cvta_generic_to_global(src)));
}
__device__ __forceinline__ void merge2(float& v1, int& i1, float& v2, int& i2,
                                       float w1, int j1, float w2, int j2) {
    if (w1 < v1) {
        float t2 = v1; int ti2 = i1;
        v1 = w1; i1 = j1;
        if (w2 < t2) { v2 = w2; i2 = j2; } else { v2 = t2; i2 = ti2; }
    } else if (w1 < v2) {
        v2 = w1; i2 = j1;
    }
}

// ---------------------------------------------------------------- ||e||^2 (exact ref rounding)
__global__ void e2_kernel(const float* __restrict__ cb) {
    int c = blockIdx.x * blockDim.x + threadIdx.x;
    if (c >= LL * GG * KK) return;
    const float* e = cb + (size_t)c * DD;
    float s = 0.0f;
    for (int d = 0; d < DD; ++d) {
        float v = e[d];
        s = __fadd_rn(s, __fmul_rn(v, v));
    }
    g_e2[c] = s;
}

// ---------------------------------------------------------------- codebook fp16 (scaled 1024x)
__global__ void eh_kernel(const float* __restrict__ cb) {
    int i = blockIdx.x * blockDim.x + threadIdx.x;
    if (i >= CBELEMS) return;
    g_eh[i] = __float2half_rn(__fmul_rn(cb[i], 1024.0f));
}

// ---------------------------------------------------------------- main
__global__ void __launch_bounds__(NTH, 1)
rvq_kernel(const float* __restrict__ xin, const float* __restrict__ cb,
           float* __restrict__ dout, unsigned long long out_size) {
    extern __shared__ char smraw[];
    __half*  Ah   = (__half*)(smraw + OFF_AH);
    __half*  Al   = (__half*)(smraw + OFF_AL);
    float*   E2s  = (float*)(smraw + OFF_E2S);
    float*   Asm  = (float*)(smraw + OFF_ASM);
    float*   PV   = (float*)(smraw + OFF_PV);
    int*     PI   = (int*)(smraw + OFF_PI);
    int*     RUNI = (int*)(smraw + OFF_RUNI);
    double*  red  = (double*)(smraw + OFF_RED);

    const unsigned smbase = (unsigned)__cvta_generic_to_shared(smraw);
    const unsigned uB[2] = {smbase + OFF_B, smbase + OFF_B + BSTAGE};

    const int tid  = threadIdx.x;
    const int lane = tid & 31;
    const int warp = tid >> 5;
    const int wm   = warp >> 2;           // 0..3  (32 token rows each)
    const int wn   = warp & 3;            // 0..3  (64 code cols each)
    const int r4   = lane >> 2;           // 0..7
    const int kq   = lane & 3;            // 0..3

    // ldmatrix lane address components (mapping verified rounds 7-15)
    const int lrowA  = (lane & 7) + (((lane >> 3) & 1) << 3);
    const int lkoffA = (lane >> 4) << 3;
    const unsigned aBaseH = smbase + OFF_AH +
        (unsigned)(((wm * 32 + lrowA) * APITCH + lkoffA) << 1);
    const unsigned aBaseL = smbase + OFF_AL +
        (unsigned)(((wm * 32 + lrowA) * APITCH + lkoffA) << 1);
    const int rB   = lane & 7;
    const int selB = (lane >> 3) & 1;
    const unsigned bLaneOff = (unsigned)(((wn * 64 + rB) * BPITCH + selB * 8) << 1);

    const int g    = blockIdx.y;
    const int tile = blockIdx.x;              // 0..511
    const int b    = tile >> 5;
    const int t0   = (tile & 31) << 7;
    const int cta  = g * 512 + tile;
    const float* xb = xin + ((size_t)b * (GG * DD) + (size_t)g * DD) * TT + t0;
    float* gX = g_X + (size_t)cta * (DD * TILE);

    // residual := xin tile, [d][t] in global scratch
    for (int i = tid; i < DD * TILE; i += NTH) {
        int d = i >> 7, t = i & 127;
        gX[i] = xb[(size_t)d * TT + t];
    }
    __syncthreads();

    double lacc = 0.0;

    for (int l = 0; l < LL; ++l) {
        const int    cbase = (l * GG + g) * KK;
        const float* cbl   = cb + (size_t)cbase * DD;

        // exact a_n = sequential fl(x^2) sum, d ascending (ref reduce order)
        if (tid < TILE) {
            float s = 0.0f;
            const float* xc = gX + tid;
#pragma unroll 8
            for (int d = 0; d < DD; ++d) {
                float v = xc[d * TILE];
                s = __fadd_rn(s, __fmul_rn(v, v));
            }
            Asm[tid] = s;
        }
        // split residual into fp16 Ah + Al (x to ~22 bits)
        for (int i = tid; i < DD * TILE; i += NTH) {
            int d = i >> 7, t = i & 127;
            float v = gX[i];
            __half h = __float2half_rn(v);
            float rlo = __fsub_rn(v, __half2float(h));
            Ah[t * APITCH + d] = h;
            Al[t * APITCH + d] = __float2half_rn(rlo);
        }
        __syncthreads();

        // per-token running top-3 (registers, tid<128)
        float t3v0 = 3.0e38f, t3v1 = 3.0e38f, t3v2 = 3.0e38f;
        int   t3i0 = 0,       t3i1 = 0,       t3i2 = 0;

        // prefetch kb=0 chunk 0 into stage 0 (2048 16B vectors)
        {
            const __half* sH = g_eh + ((size_t)cbase) * DD;
#pragma unroll
            for (int it = 0; it < 4; ++it) {
                int v = tid + it * NTH;               // 0..2047
                int code = v >> 3, d8 = (v & 7) * 8;
                cpasync16(uB[0] + (unsigned)((code * BPITCH + d8) << 1),
                          sH + (size_t)code * DD + d8);
            }
            asm volatile("cp.async.commit_group;");
        }

        for (int kb = 0; kb < 4; ++kb) {               // 4 blocks of 256 codes
            const size_t gbBlk = ((size_t)(cbase + kb * 256)) * DD;
            if (tid < 256) E2s[tid] = g_e2[cbase + kb * 256 + tid];

            float acc[2][8][4];
#pragma unroll
            for (int mt = 0; mt < 2; ++mt)
#pragma unroll
                for (int nt = 0; nt < 8; ++nt)
#pragma unroll
                    for (int e = 0; e < 4; ++e) acc[mt][nt][e] = 0.f;

#pragma unroll 1
            for (int kc = 0; kc < 4; ++kc) {           // 4 d-chunks of 64
                if (kc < 3) {                          // prefetch next chunk
                    const __half* sH = g_eh + gbBlk + (kc + 1) * 64;
                    unsigned dh = uB[(kc + 1) & 1];
#pragma unroll
                    for (int it = 0; it < 4; ++it) {
                        int v = tid + it * NTH;       // 0..2047
                        int code = v >> 3, d8 = (v & 7) * 8;
                        cpasync16(dh + (unsigned)((code * BPITCH + d8) << 1),
                                  sH + (size_t)code * DD + d8);
                    }
                    asm volatile("cp.async.commit_group;");
                    asm volatile("cp.async.wait_group 1;");
                } else {
                    asm volatile("cp.async.wait_group 0;");
                }
                __syncthreads();

                const unsigned b_st = uB[kc & 1] + bLaneOff;
#pragma unroll
                for (int ks = 0; ks < 4; ++ks) {       // k16 steps
                    const unsigned akoff = (unsigned)((kc * 64 + ks * 16) << 1);
                    const unsigned bkoff = (unsigned)((ks * 16) << 1);
                    unsigned ah[2][4], al[2][4];
#pragma unroll
                    for (int mt = 0; mt < 2; ++mt) {
                        ldsm_x4(ah[mt], aBaseH + (unsigned)(mt * 16 * APITCH * 2) + akoff);
                        ldsm_x4(al[mt], aBaseL + (unsigned)(mt * 16 * APITCH * 2) + akoff);
                    }
#pragma unroll
                    for (int nh = 0; nh < 2; ++nh) {   // two nt-halves: fewer live regs
                        unsigned bh[4][2];
#pragma unroll
                        for (int n4 = 0; n4 < 4; ++n4)
                            ldsm_x2(bh[n4], b_st +
                                    (unsigned)(((nh * 4 + n4) * 8 * BPITCH) << 1) + bkoff);
#pragma unroll
                        for (int mt = 0; mt < 2; ++mt)
#pragma unroll
                            for (int n4 = 0; n4 < 4; ++n4) {
                                mma16816h(acc[mt][nh * 4 + n4], ah[mt], bh[n4]);
                                mma16816h(acc[mt][nh * 4 + n4], al[mt], bh[n4]);
                            }
                    }
                }
                __syncthreads();
            }

            // cross-kb prefetch of next block's chunk 0 into stage 0
            if (kb < 3) {
                const __half* sH = g_eh + ((size_t)(cbase + (kb + 1) * 256)) * DD;
#pragma unroll
                for (int it = 0; it < 4; ++it) {
                    int v = tid + it * NTH;           // 0..2047
                    int code = v >> 3, d8 = (v & 7) * 8;
                    cpasync16(uB[0] + (unsigned)((code * BPITCH + d8) << 1),
                              sH + (size_t)code * DD + d8);
                }
                asm volatile("cp.async.commit_group;");
            }

            // epilogue: distances + per-warp per-row top2 (over 64 cols)
#pragma unroll
            for (int mt = 0; mt < 2; ++mt)
#pragma unroll
                for (int h = 0; h < 2; ++h) {
                    int row = wm * 32 + mt * 16 + h * 8 + r4;
                    float a_tok = Asm[row];
                    float w1 = 3.0e38f, w2 = 3.0e38f; int j1 = 0, j2 = 0;
#pragma unroll
                    for (int nt = 0; nt < 8; ++nt)
#pragma unroll
                        for (int j = 0; j < 2; ++j) {
                            int colq = wn * 64 + nt * 8 + 2 * kq + j;
                            float c = acc[mt][nt][h * 2 + j];
                            // d~ = fl( fl(a+b) - 2*(c~/1024) ), scale exact
                            float dv = __fadd_rn(__fadd_rn(a_tok, E2s[colq]),
                                                 __fmul_rn(c, -0.001953125f));
                            int idx = kb * 256 + colq;
                            if (dv < w1) { w2 = w1; j2 = j1; w1 = dv; j1 = idx; }
                            else if (dv < w2) { w2 = dv; j2 = idx; }
                        }
#pragma unroll
                    for (int s = 1; s <= 2; s <<= 1) {
                        float u1 = __shfl_xor_sync(0xffffffffu, w1, s);
                        int   k1 = __shfl_xor_sync(0xffffffffu, j1, s);
                        float u2 = __shfl_xor_sync(0xffffffffu, w2, s);
                        int   k2 = __shfl_xor_sync(0xffffffffu, j2, s);
                        merge2(w1, j1, w2, j2, u1, k1, u2, k2);
                    }
                    if (kq == 0) {
                        PV[row * 8 + wn * 2 + 0] = w1;  PI[row * 8 + wn * 2 + 0] = j1;
                        PV[row * 8 + wn * 2 + 1] = w2;  PI[row * 8 + wn * 2 + 1] = j2;
                    }
                }
            __syncthreads();
            if (tid < TILE) {                          // merge 8 partials into top3
#pragma unroll
                for (int e = 0; e < 8; ++e) {
                    float v = PV[tid * 8 + e]; int i = PI[tid * 8 + e];
                    if (v < t3v0) { t3v2 = t3v1; t3i2 = t3i1; t3v1 = t3v0; t3i1 = t3i0;
                                    t3v0 = v; t3i0 = i; }
                    else if (v < t3v1) { t3v2 = t3v1; t3i2 = t3i1; t3v1 = v; t3i1 = i; }
                    else if (v < t3v2) { t3v2 = v; t3i2 = i; }
                }
            }
            __syncthreads();
        }

        // finalize winner: sound margin; exact re-score for ambiguous tokens
        if (tid < TILE) {
            float a_tok  = Asm[tid];
            float margin = __fmaf_rn(a_tok, 2.4e-7f, 1.0e-5f);
            int winner = t3i0;
            if (t3v1 <= t3v0 + margin) {
                int ci[3]; int nc = 0;
                ci[nc++] = t3i0;
                ci[nc++] = t3i1;
                if (t3v2 <= t3v0 + margin) ci[nc++] = t3i2;
                if (nc == 3) {
                    int a0 = ci[0], a1 = ci[1], a2 = ci[2], t;
                    if (a1 < a0) { t = a0; a0 = a1; a1 = t; }
                    if (a2 < a1) { t = a1; a1 = a2; a2 = t; }
                    if (a1 < a0) { t = a0; a0 = a1; a1 = t; }
                    ci[0] = a0; ci[1] = a1; ci[2] = a2;
                } else if (ci[1] < ci[0]) { int t = ci[0]; ci[0] = ci[1]; ci[1] = t; }
                float best = 3.0e38f; winner = ci[0];
                for (int cc = 0; cc < nc; ++cc) {
                    int code = ci[cc];
                    const float* ev = cbl + (size_t)code * DD;
                    const float* xc = gX + tid;
                    float c = 0.0f;
#pragma unroll 8
                    for (int d = 0; d < DD; ++d)
                        c = __fmaf_rn(xc[d * TILE], ev[d], c);
                    float dv = __fadd_rn(__fadd_rn(a_tok, g_e2[cbase + code]),
                                         __fmul_rn(-2.0f, c));
                    if (dv < best) { best = dv; winner = code; }
                }
            }
            RUNI[tid] = winner;
            if (out_size > IDX_OFF) {
                size_t n = (size_t)b * TT + t0 + tid;
                size_t o = IDX_OFF + ((size_t)(l * GG + g)) * NTOK + n;
                if (o < out_size) dout[o] = (float)winner;
            }
        }
        __syncthreads();

        // residual update (reference STE elementwise)
        {
            int token = tid >> 2, dq = tid & 3;
            int code  = RUNI[token];
            const float* ev = cbl + (size_t)code * DD + dq * 64;
            float* xc = gX + (dq * 64) * TILE + token;
#pragma unroll 8
            for (int dd = 0; dd < 64; ++dd) {
                float x  = xc[dd * TILE];
                float dl = __fsub_rn(ev[dd], x);
                float qn = __fadd_rn(x, dl);
                xc[dd * TILE] = __fsub_rn(x, qn);
                lacc += (double)dl * (double)dl;
            }
        }
        __syncthreads();
    }

    // quantized_out = xin - final residual
    for (int i = tid; i < DD * TILE; i += NTH) {
        int d = i >> 7, t = i & 127;
        size_t o = ((size_t)b * (GG * DD) + (size_t)g * DD + d) * TT + t0 + t;
        if (o < out_size && o < QOUT_ELEMS)
            dout[o] = __fsub_rn(xb[(size_t)d * TT + t], gX[i]);
    }

    // deterministic per-CTA loss partial
    red[tid] = lacc;
    __syncthreads();
    for (int s = 256; s > 0; s >>= 1) {
        if (tid < s) red[tid] += red[tid + s];
        __syncthreads();
    }
    if (tid == 0) g_loss[cta] = red[0];
}

// ---------------------------------------------------------------- loss reduce
__global__ void loss_kernel(float* __restrict__ dout, unsigned long long out_size) {
    __shared__ double red[256];
    int tid = threadIdx.x;
    double s = 0.0;
    for (int i = tid; i < NCTA; i += 256) s += g_loss[i];
    red[tid] = s;
    __syncthreads();
    for (int st = 128; st > 0; st >>= 1) {
        if (tid < st) red[tid] += red[tid + st];
        __syncthreads();
    }
    if (tid == 0 && out_size > LOSS_OFF)
        dout[LOSS_OFF] = (float)(1.25 * red[0] / (8.0 * 33554432.0));
}

// ---------------------------------------------------------------- launch
extern "C" void kernel_launch(void* const* d_in, const int* in_sizes, int n_in,
                              void* d_out, int out_size) {
    const float* xin = (const float*)d_in[0];
    const float* cb  = (const float*)d_in[1];
    if (n_in >= 2 && in_sizes[0] == CBELEMS) {
        xin = (const float*)d_in[1];
        cb  = (const float*)d_in[0];
    }
    float* dout = (float*)d_out;
    unsigned long long osz = (unsigned long long)out_size;

    static bool attr_set = false;
    if (!attr_set) {
        cudaFuncSetAttribute(rvq_kernel, cudaFuncAttributeMaxDynamicSharedMemorySize,
                             SMEM_TOT);
        attr_set = true;
    }

    e2_kernel<<<(LL * GG * KK + 255) / 256, 256>>>(cb);
    eh_kernel<<<(CBELEMS + 255) / 256, 256>>>(cb);
    dim3 grid(512, GG);
    rvq_kernel<<<grid, NTH, SMEM_TOT>>>(xin, cb, dout, osz);
    loss_kernel<<<1, 256>>>(dout, osz);
}

// round 17
// speedup vs baseline: 2.9158x; 1.2605x over previous
#include <cuda_runtime.h>
#include <cuda_fp16.h>

// Residual VQ (L=8, G=2, K=1024, D=256), B=16, T=4096, N=65536.
// 1-term fp16 MMA screening: Ah = fl16(x), Eh = fl16(1024*e);
// c~ = Ah*Eh (fp32 accum), d~ = fl(fl(a+b) - 2*c~/1024)  [scale exact].
// Error sigma ~4e-6 << margin (a*2.4e-7+1e-5 ~ 17 sigma). Sound margin ->
// <=3 candidates -> exact fp32 reference-semantics rescue (sequential
// d-ascending FMA chain, d = fl(fl(a+b)-2c), first-index argmin).
// Skeleton: 512 thr / 16 warps, 256-code blocks, cp.async double buffer +
// cross-kb prefetch, ldmatrix, shuffle top-2 epilogue, global-scratch X.
// a_n chain (tid<128) overlapped with Ah split (tid>=128).

#define LL 8
#define GG 2
#define KK 1024
#define DD 256
#define TT 4096
#define NTOK 65536ull
#define TILE 128
#define NTH 512
#define APITCH 264      // fp16 per A row (256 + 8 pad) -> 528B
#define BPITCH 72       // fp16 per B row (64 + 8 pad)  -> 144B
#define BSTAGE 36864    // 256 codes * BPITCH * 2B (one stage)

#define QOUT_ELEMS 33554432ull
#define LOSS_OFF   33554432ull
#define IDX_OFF    33554433ull

#define CBELEMS (LL * GG * KK * DD)
#define NCTA 1024

// smem byte offsets
#define OFF_AH   0          // fp16 [128][264]  67584
#define OFF_B    67584      // 2 stages x 36864 = 73728
#define OFF_E2S  141312     // fp32 [256]
#define OFF_ASM  142336     // fp32 [128]
#define OFF_PV   142848     // fp32 [128][8]
#define OFF_PI   146944     // int  [128][8]
#define OFF_RUNI 151040     // int  [128]
#define OFF_RED  151552     // double [512]
#define SMEM_TOT 155648

__device__ float   g_e2[LL * GG * KK];
__device__ double  g_loss[NCTA];
__device__ __half  g_eh[CBELEMS];                          // fl16(1024 * e)
__device__ float   g_X[(size_t)NCTA * DD * TILE];          // per-CTA residual [d][t]

// ---------------------------------------------------------------- asm helpers
__device__ __forceinline__ void mma16816h(float* c, const unsigned* a, const unsigned* b) {
    asm volatile(
        "mma.sync.aligned.m16n8k16.row.col.f32.f16.f16.f32 "
        "{%0,%1,%2,%3},{%4,%5,%6,%7},{%8,%9},{%0,%1,%2,%3};"
        : "+f"(c[0]), "+f"(c[1]), "+f"(c[2]), "+f"(c[3])
        : "r"(a[0]), "r"(a[1]), "r"(a[2]), "r"(a[3]), "r"(b[0]), "r"(b[1]));
}
__device__ __forceinline__ void ldsm_x4(unsigned* r, unsigned addr) {
    asm volatile("ldmatrix.sync.aligned.m8n8.x4.shared.b16 {%0,%1,%2,%3},[%4];"
                 : "=r"(r[0]), "=r"(r[1]), "=r"(r[2]), "=r"(r[3]) : "r"(addr));
}
__device__ __forceinline__ void ldsm_x2(unsigned* r, unsigned addr) {
    asm volatile("ldmatrix.sync.aligned.m8n8.x2.shared.b16 {%0,%1},[%2];"
                 : "=r"(r[0]), "=r"(r[1]) : "r"(addr));
}
__device__ __forceinline__ void cpasync16(unsigned dst, const void* src) {
    asm volatile("cp.async.cg.shared.global [%0], [%1], 16;"
                 :: "r"(dst), "l"(__cvta_generic_to_global(src)));
}
__device__ __forceinline__ void merge2(float& v1, int& i1, float& v2, int& i2,
                                       float w1, int j1, float w2, int j2) {
    if (w1 < v1) {
        float t2 = v1; int ti2 = i1;
        v1 = w1; i1 = j1;
        if (w2 < t2) { v2 = w2; i2 = j2; } else { v2 = t2; i2 = ti2; }
    } else if (w1 < v2) {
        v2 = w1; i2 = j1;
    }
}

// ---------------------------------------------------------------- ||e||^2 (exact ref rounding)
__global__ void e2_kernel(const float* __restrict__ cb) {
    int c = blockIdx.x * blockDim.x + threadIdx.x;
    if (c >= LL * GG * KK) return;
    const float* e = cb + (size_t)c * DD;
    float s = 0.0f;
    for (int d = 0; d < DD; ++d) {
        float v = e[d];
        s = __fadd_rn(s, __fmul_rn(v, v));
    }
    g_e2[c] = s;
}

// ---------------------------------------------------------------- codebook fp16 (scaled 1024x)
__global__ void eh_kernel(const float* __restrict__ cb) {
    int i = blockIdx.x * blockDim.x + threadIdx.x;
    if (i >= CBELEMS) return;
    g_eh[i] = __float2half_rn(__fmul_rn(cb[i], 1024.0f));
}

// ---------------------------------------------------------------- main
__global__ void __launch_bounds__(NTH, 1)
rvq_kernel(const float* __restrict__ xin, const float* __restrict__ cb,
           float* __restrict__ dout, unsigned long long out_size) {
    extern __shared__ char smraw[];
    __half*  Ah   = (__half*)(smraw + OFF_AH);
    float*   E2s  = (float*)(smraw + OFF_E2S);
    float*   Asm  = (float*)(smraw + OFF_ASM);
    float*   PV   = (float*)(smraw + OFF_PV);
    int*     PI   = (int*)(smraw + OFF_PI);
    int*     RUNI = (int*)(smraw + OFF_RUNI);
    double*  red  = (double*)(smraw + OFF_RED);

    const unsigned smbase = (unsigned)__cvta_generic_to_shared(smraw);
    const unsigned uB[2] = {smbase + OFF_B, smbase + OFF_B + BSTAGE};

    const int tid  = threadIdx.x;
    const int lane = tid & 31;
    const int warp = tid >> 5;
    const int wm   = warp >> 2;           // 0..3  (32 token rows each)
    const int wn   = warp & 3;            // 0..3  (64 code cols each)
    const int r4   = lane >> 2;           // 0..7
    const int kq   = lane & 3;            // 0..3

    // ldmatrix lane address components (mapping verified rounds 7-16)
    const int lrowA  = (lane & 7) + (((lane >> 3) & 1) << 3);
    const int lkoffA = (lane >> 4) << 3;
    const unsigned aBaseH = smbase + OFF_AH +
        (unsigned)(((wm * 32 + lrowA) * APITCH + lkoffA) << 1);
    const int rB   = lane & 7;
    const int selB = (lane >> 3) & 1;
    const unsigned bLaneOff = (unsigned)(((wn * 64 + rB) * BPITCH + selB * 8) << 1);

    const int g    = blockIdx.y;
    const int tile = blockIdx.x;              // 0..511
    const int b    = tile >> 5;
    const int t0   = (tile & 31) << 7;
    const int cta  = g * 512 + tile;
    const float* xb = xin + ((size_t)b * (GG * DD) + (size_t)g * DD) * TT + t0;
    float* gX = g_X + (size_t)cta * (DD * TILE);

    // residual := xin tile, [d][t] in global scratch
    for (int i = tid; i < DD * TILE; i += NTH) {
        int d = i >> 7, t = i & 127;
        gX[i] = xb[(size_t)d * TT + t];
    }
    __syncthreads();

    double lacc = 0.0;

    for (int l = 0; l < LL; ++l) {
        const int    cbase = (l * GG + g) * KK;
        const float* cbl   = cb + (size_t)cbase * DD;

        // OVERLAPPED: a_n exact chain (tid<128) || Ah split (tid>=128)
        if (tid < TILE) {
            float s = 0.0f;
            const float* xc = gX + tid;
#pragma unroll 8
            for (int d = 0; d < DD; ++d) {
                float v = xc[d * TILE];
                s = __fadd_rn(s, __fmul_rn(v, v));
            }
            Asm[tid] = s;
        } else {
            for (int i = tid - TILE; i < DD * TILE; i += NTH - TILE) {
                int d = i >> 7, t = i & 127;
                Ah[t * APITCH + d] = __float2half_rn(gX[i]);
            }
        }
        __syncthreads();

        // per-token running top-3 (registers, tid<128)
        float t3v0 = 3.0e38f, t3v1 = 3.0e38f, t3v2 = 3.0e38f;
        int   t3i0 = 0,       t3i1 = 0,       t3i2 = 0;

        // prefetch kb=0 chunk 0 into stage 0 (2048 16B vectors)
        {
            const __half* sH = g_eh + ((size_t)cbase) * DD;
#pragma unroll
            for (int it = 0; it < 4; ++it) {
                int v = tid + it * NTH;               // 0..2047
                int code = v >> 3, d8 = (v & 7) * 8;
                cpasync16(uB[0] + (unsigned)((code * BPITCH + d8) << 1),
                          sH + (size_t)code * DD + d8);
            }
            asm volatile("cp.async.commit_group;");
        }

        for (int kb = 0; kb < 4; ++kb) {               // 4 blocks of 256 codes
            const size_t gbBlk = ((size_t)(cbase + kb * 256)) * DD;
            if (tid < 256) E2s[tid] = g_e2[cbase + kb * 256 + tid];

            float acc[2][8][4];
#pragma unroll
            for (int mt = 0; mt < 2; ++mt)
#pragma unroll
                for (int nt = 0; nt < 8; ++nt)
#pragma unroll
                    for (int e = 0; e < 4; ++e) acc[mt][nt][e] = 0.f;

#pragma unroll 1
            for (int kc = 0; kc < 4; ++kc) {           // 4 d-chunks of 64
                if (kc < 3) {                          // prefetch next chunk
                    const __half* sH = g_eh + gbBlk + (kc + 1) * 64;
                    unsigned dh = uB[(kc + 1) & 1];
#pragma unroll
                    for (int it = 0; it < 4; ++it) {
                        int v = tid + it * NTH;       // 0..2047
                        int code = v >> 3, d8 = (v & 7) * 8;
                        cpasync16(dh + (unsigned)((code * BPITCH + d8) << 1),
                                  sH + (size_t)code * DD + d8);
                    }
                    asm volatile("cp.async.commit_group;");
                    asm volatile("cp.async.wait_group 1;");
                } else {
                    asm volatile("cp.async.wait_group 0;");
                }
                __syncthreads();

                const unsigned b_st = uB[kc & 1] + bLaneOff;
#pragma unroll
                for (int ks = 0; ks < 4; ++ks) {       // k16 steps
                    const unsigned akoff = (unsigned)((kc * 64 + ks * 16) << 1);
                    const unsigned bkoff = (unsigned)((ks * 16) << 1);
                    unsigned ah[2][4];
#pragma unroll
                    for (int mt = 0; mt < 2; ++mt)
                        ldsm_x4(ah[mt], aBaseH + (unsigned)(mt * 16 * APITCH * 2) + akoff);
#pragma unroll
                    for (int nh = 0; nh < 2; ++nh) {   // two nt-halves
                        unsigned bh[4][2];
#pragma unroll
                        for (int n4 = 0; n4 < 4; ++n4)
                            ldsm_x2(bh[n4], b_st +
                                    (unsigned)(((nh * 4 + n4) * 8 * BPITCH) << 1) + bkoff);
#pragma unroll
                        for (int mt = 0; mt < 2; ++mt)
#pragma unroll
                            for (int n4 = 0; n4 < 4; ++n4)
                                mma16816h(acc[mt][nh * 4 + n4], ah[mt], bh[n4]);
                    }
                }
                __syncthreads();
            }

            // cross-kb prefetch of next block's chunk 0 into stage 0
            if (kb < 3) {
                const __half* sH = g_eh + ((size_t)(cbase + (kb + 1) * 256)) * DD;
#pragma unroll
                for (int it = 0; it < 4; ++it) {
                    int v = tid + it * NTH;           // 0..2047
                    int code = v >> 3, d8 = (v & 7) * 8;
                    cpasync16(uB[0] + (unsigned)((code * BPITCH + d8) << 1),
                              sH + (size_t)code * DD + d8);
                }
                asm volatile("cp.async.commit_group;");
            }

            // epilogue: distances + per-warp per-row top2 (over 64 cols)
#pragma unroll
            for (int mt = 0; mt < 2; ++mt)
#pragma unroll
                for (int h = 0; h < 2; ++h) {
                    int row = wm * 32 + mt * 16 + h * 8 + r4;
                    float a_tok = Asm[row];
                    float w1 = 3.0e38f, w2 = 3.0e38f; int j1 = 0, j2 = 0;
#pragma unroll
                    for (int nt = 0; nt < 8; ++nt)
#pragma unroll
                        for (int j = 0; j < 2; ++j) {
                            int colq = wn * 64 + nt * 8 + 2 * kq + j;
                            float c = acc[mt][nt][h * 2 + j];
                            // d~ = fl( fl(a+b) - 2*(c~/1024) ), scale exact
                            float dv = __fadd_rn(__fadd_rn(a_tok, E2s[colq]),
                                                 __fmul_rn(c, -0.001953125f));
                            int idx = kb * 256 + colq;
                            if (dv < w1) { w2 = w1; j2 = j1; w1 = dv; j1 = idx; }
                            else if (dv < w2) { w2 = dv; j2 = idx; }
                        }
#pragma unroll
                    for (int s = 1; s <= 2; s <<= 1) {
                        float u1 = __shfl_xor_sync(0xffffffffu, w1, s);
                        int   k1 = __shfl_xor_sync(0xffffffffu, j1, s);
                        float u2 = __shfl_xor_sync(0xffffffffu, w2, s);
                        int   k2 = __shfl_xor_sync(0xffffffffu, j2, s);
                        merge2(w1, j1, w2, j2, u1, k1, u2, k2);
                    }
                    if (kq == 0) {
                        PV[row * 8 + wn * 2 + 0] = w1;  PI[row * 8 + wn * 2 + 0] = j1;
                        PV[row * 8 + wn * 2 + 1] = w2;  PI[row * 8 + wn * 2 + 1] = j2;
                    }
                }
            __syncthreads();
            if (tid < TILE) {                          // merge 8 partials into top3
#pragma unroll
                for (int e = 0; e < 8; ++e) {
                    float v = PV[tid * 8 + e]; int i = PI[tid * 8 + e];
                    if (v < t3v0) { t3v2 = t3v1; t3i2 = t3i1; t3v1 = t3v0; t3i1 = t3i0;
                                    t3v0 = v; t3i0 = i; }
                    else if (v < t3v1) { t3v2 = t3v1; t3i2 = t3i1; t3v1 = v; t3i1 = i; }
                    else if (v < t3v2) { t3v2 = v; t3i2 = i; }
                }
            }
            __syncthreads();
        }

        // finalize winner: sound margin; exact re-score for ambiguous tokens
        if (tid < TILE) {
            float a_tok  = Asm[tid];
            float margin = __fmaf_rn(a_tok, 2.4e-7f, 1.0e-5f);
            int winner = t3i0;
            if (t3v1 <= t3v0 + margin) {
                int ci[3]; int nc = 0;
                ci[nc++] = t3i0;
                ci[nc++] = t3i1;
                if (t3v2 <= t3v0 + margin) ci[nc++] = t3i2;
                if (nc == 3) {
                    int a0 = ci[0], a1 = ci[1], a2 = ci[2], t;
                    if (a1 < a0) { t = a0; a0 = a1; a1 = t; }
                    if (a2 < a1) { t = a1; a1 = a2; a2 = t; }
                    if (a1 < a0) { t = a0; a0 = a1; a1 = t; }
                    ci[0] = a0; ci[1] = a1; ci[2] = a2;
                } else if (ci[1] < ci[0]) { int t = ci[0]; ci[0] = ci[1]; ci[1] = t; }
                float best = 3.0e38f; winner = ci[0];
                for (int cc = 0; cc < nc; ++cc) {
                    int code = ci[cc];
                    const float* ev = cbl + (size_t)code * DD;
                    const float* xc = gX + tid;
                    float c = 0.0f;
#pragma unroll 8
                    for (int d = 0; d < DD; ++d)
                        c = __fmaf_rn(xc[d * TILE], ev[d], c);
                    float dv = __fadd_rn(__fadd_rn(a_tok, g_e2[cbase + code]),
                                         __fmul_rn(-2.0f, c));
                    if (dv < best) { best = dv; winner = code; }
                }
            }
            RUNI[tid] = winner;
            if (out_size > IDX_OFF) {
                size_t n = (size_t)b * TT + t0 + tid;
                size_t o = IDX_OFF + ((size_t)(l * GG + g)) * NTOK + n;
                if (o < out_size) dout[o] = (float)winner;
            }
        }
        __syncthreads();

        // residual update (reference STE elementwise)
        {
            int token = tid >> 2, dq = tid & 3;
            int code  = RUNI[token];
            const float* ev = cbl + (size_t)code * DD + dq * 64;
            float* xc = gX + (dq * 64) * TILE + token;
#pragma unroll 8
            for (int dd = 0; dd < 64; ++dd) {
                float x  = xc[dd * TILE];
                float dl = __fsub_rn(ev[dd], x);
                float qn = __fadd_rn(x, dl);
                xc[dd * TILE] = __fsub_rn(x, qn);
                lacc += (double)dl * (double)dl;
            }
        }
        __syncthreads();
    }

    // quantized_out = xin - final residual
    for (int i = tid; i < DD * TILE; i += NTH) {
        int d = i >> 7, t = i & 127;
        size_t o = ((size_t)b * (GG * DD) + (size_t)g * DD + d) * TT + t0 + t;
        if (o < out_size && o < QOUT_ELEMS)
            dout[o] = __fsub_rn(xb[(size_t)d * TT + t], gX[i]);
    }

    // deterministic per-CTA loss partial
    red[tid] = lacc;
    __syncthreads();
    for (int s = 256; s > 0; s >>= 1) {
        if (tid < s) red[tid] += red[tid + s];
        __syncthreads();
    }
    if (tid == 0) g_loss[cta] = red[0];
}

// ---------------------------------------------------------------- loss reduce
__global__ void loss_kernel(float* __restrict__ dout, unsigned long long out_size) {
    __shared__ double red[256];
    int tid = threadIdx.x;
    double s = 0.0;
    for (int i = tid; i < NCTA; i += 256) s += g_loss[i];
    red[tid] = s;
    __syncthreads();
    for (int st = 128; st > 0; st >>= 1) {
        if (tid < st) red[tid] += red[tid + st];
        __syncthreads();
    }
    if (tid == 0 && out_size > LOSS_OFF)
        dout[LOSS_OFF] = (float)(1.25 * red[0] / (8.0 * 33554432.0));
}

// ---------------------------------------------------------------- launch
extern "C" void kernel_launch(void* const* d_in, const int* in_sizes, int n_in,
                              void* d_out, int out_size) {
    const float* xin = (const float*)d_in[0];
    const float* cb  = (const float*)d_in[1];
    if (n_in >= 2 && in_sizes[0] == CBELEMS) {
        xin = (const float*)d_in[1];
        cb  = (const float*)d_in[0];
    }
    float* dout = (float*)d_out;
    unsigned long long osz = (unsigned long long)out_size;

    static bool attr_set = false;
    if (!attr_set) {
        cudaFuncSetAttribute(rvq_kernel, cudaFuncAttributeMaxDynamicSharedMemorySize,
                             SMEM_TOT);
        attr_set = true;
    }

    e2_kernel<<<(LL * GG * KK + 255) / 256, 256>>>(cb);
    eh_kernel<<<(CBELEMS + 255) / 256, 256>>>(cb);
    dim3 grid(512, GG);
    rvq_kernel<<<grid, NTH, SMEM_TOT>>>(xin, cb, dout, osz);
    loss_kernel<<<1, 256>>>(dout, osz);
}